// round 4
// baseline (speedup 1.0000x reference)
#include <cuda_runtime.h>
#include <cuda_bf16.h>
#include <cstdint>

#define Bb 32
#define Vv 5
#define Nn 196
#define Cc 768
#define Hh 768
#define BN_ROWS 6272            // Bb*Nn
#define BVN 31360               // Bb*Vv*Nn
#define NUM_ITERS 3
#define WMAT (Cc*Cc)            // 589824

// ---------------------------------------------------------------------------
// Scratch (device globals; no runtime allocation allowed)
// ---------------------------------------------------------------------------
__device__ float g_P[(size_t)BVN * Cc];        // proj_x   fp32
__device__ float g_XW1[(size_t)BVN * Hh];      // x @ w1[:C]
__device__ float g_CW1[(size_t)BN_ROWS * Hh];  // c @ w1[C:]
__device__ float g_S[BVN];                     // scores
__device__ __nv_bfloat16 g_xh[(size_t)BVN * Cc];
__device__ __nv_bfloat16 g_xl[(size_t)BVN * Cc];
__device__ __nv_bfloat16 g_ch[(size_t)BN_ROWS * Cc];
__device__ __nv_bfloat16 g_cl[(size_t)BN_ROWS * Cc];
// 7 transposed [N,K] weight matrices: views 0..4, w1a=5, w1b=6
__device__ __nv_bfloat16 g_Wh[(size_t)7 * WMAT];
__device__ __nv_bfloat16 g_Wl[(size_t)7 * WMAT];

// ---------------------------------------------------------------------------
// Helpers
// ---------------------------------------------------------------------------
__device__ __forceinline__ uint32_t su32(const void* p) {
    uint32_t a;
    asm("{ .reg .u64 t; cvta.to.shared.u64 t, %1; cvt.u32.u64 %0, t; }" : "=r"(a) : "l"(p));
    return a;
}
__device__ __forceinline__ void cpa16(uint32_t d, const void* s) {
    asm volatile("cp.async.cg.shared.global [%0], [%1], 16;" :: "r"(d), "l"(s) : "memory");
}
__device__ __forceinline__ void cp_commit() {
    asm volatile("cp.async.commit_group;" ::: "memory");
}
__device__ __forceinline__ void ldsm4(uint32_t& r0, uint32_t& r1, uint32_t& r2, uint32_t& r3,
                                      uint32_t addr) {
    asm volatile("ldmatrix.sync.aligned.m8n8.x4.shared.b16 {%0,%1,%2,%3}, [%4];"
                 : "=r"(r0), "=r"(r1), "=r"(r2), "=r"(r3) : "r"(addr));
}
__device__ __forceinline__ void mma16816(float* d, const uint32_t* a, const uint32_t* b) {
    asm volatile(
        "mma.sync.aligned.m16n8k16.row.col.f32.bf16.bf16.f32 "
        "{%0,%1,%2,%3}, {%4,%5,%6,%7}, {%8,%9}, {%0,%1,%2,%3};"
        : "+f"(d[0]), "+f"(d[1]), "+f"(d[2]), "+f"(d[3])
        : "r"(a[0]), "r"(a[1]), "r"(a[2]), "r"(a[3]), "r"(b[0]), "r"(b[1]));
}

__device__ __forceinline__ void split1(float a, uint16_t& h, uint16_t& l) {
    __nv_bfloat16 bh = __float2bfloat16(a);
    __nv_bfloat16 bl = __float2bfloat16(a - __bfloat162float(bh));
    h = *(uint16_t*)&bh;
    l = *(uint16_t*)&bl;
}

// ---------------------------------------------------------------------------
// Split x into bf16 hi/lo
// ---------------------------------------------------------------------------
__global__ void split_x_kernel(const float* __restrict__ x) {
    size_t i = (size_t)blockIdx.x * blockDim.x + threadIdx.x;
    const size_t TOT = (size_t)BVN * Cc / 4;
    if (i >= TOT) return;
    float4 v = *(const float4*)(x + i * 4);
    union { uint16_t u[4]; uint2 p; } hh, ll;
    split1(v.x, hh.u[0], ll.u[0]);
    split1(v.y, hh.u[1], ll.u[1]);
    split1(v.z, hh.u[2], ll.u[2]);
    split1(v.w, hh.u[3], ll.u[3]);
    *(uint2*)(g_xh + i * 4) = hh.p;
    *(uint2*)(g_xl + i * 4) = ll.p;
}

// ---------------------------------------------------------------------------
// Transpose + split weights into g_Wh/g_Wl ([N,K] K-major, 7 matrices)
// ---------------------------------------------------------------------------
__global__ void split_w_kernel(const float* __restrict__ w_views, const float* __restrict__ w1) {
    size_t j = (size_t)blockIdx.x * blockDim.x + threadIdx.x;
    const size_t TOT = (size_t)7 * WMAT;
    if (j >= TOT) return;
    int m = (int)(j / WMAT);
    int r = (int)(j % WMAT);
    int n = r / Cc, k = r % Cc;
    float s;
    if (m < 5)       s = w_views[(size_t)m * WMAT + (size_t)k * Cc + n];
    else if (m == 5) s = w1[(size_t)k * Hh + n];
    else             s = w1[(size_t)(Cc + k) * Hh + n];
    uint16_t h, l;
    split1(s, h, l);
    *(uint16_t*)(g_Wh + j) = h;
    *(uint16_t*)(g_Wl + j) = l;
}

// ---------------------------------------------------------------------------
// Mean over views -> c0 as bf16 hi/lo
// ---------------------------------------------------------------------------
__global__ void mean_kernel(const float* __restrict__ x) {
    int i = blockIdx.x * blockDim.x + threadIdx.x;
    const int TOT = BN_ROWS * (Cc / 4);
    if (i >= TOT) return;
    int bn = i / (Cc / 4);
    int cq = (i % (Cc / 4)) * 4;
    int b = bn / Nn, n = bn % Nn;
    float4 acc = make_float4(0.f, 0.f, 0.f, 0.f);
#pragma unroll
    for (int v = 0; v < Vv; v++) {
        const float4 xv = *(const float4*)(x + ((size_t)((b * Vv + v) * Nn + n)) * Cc + cq);
        acc.x += xv.x; acc.y += xv.y; acc.z += xv.z; acc.w += xv.w;
    }
    const float s = 1.0f / Vv;
    acc.x *= s; acc.y *= s; acc.z *= s; acc.w *= s;
    union { uint16_t u[4]; uint2 p; } hh, ll;
    split1(acc.x, hh.u[0], ll.u[0]);
    split1(acc.y, hh.u[1], ll.u[1]);
    split1(acc.z, hh.u[2], ll.u[2]);
    split1(acc.w, hh.u[3], ll.u[3]);
    size_t o = (size_t)bn * Cc + cq;
    *(uint2*)(g_ch + o) = hh.p;
    *(uint2*)(g_cl + o) = ll.p;
}

// ---------------------------------------------------------------------------
// mma.sync bf16x3 GEMM: Cout[M,768], CTA tile 128x128, K=768 in 24 chunks of 32.
// Stage (32KB) packs hi|lo in each 128B row: A-tile 128x[Ah64|Al64],
// B-tile 128x[Bh64|Bl64]. 3-stage cp.async pipeline (96KB) -> 2 CTAs/SM.
// 8 warps (2M x 4N), warp tile 64x32.
// MODE 0: flat rows. MODE 1: per-view gather/scatter (v = blockIdx.z).
// ---------------------------------------------------------------------------
#define STAGE_BYTES 32768          // A 16KB + B 16KB
#define NSTAGE 3
#define SMEM_TOTAL (NSTAGE * STAGE_BYTES)
#define OFF_B 16384
#define NCHUNK 24

template <int MODE>
__global__ __launch_bounds__(256, 2)
void mma_gemm(const __nv_bfloat16* __restrict__ Ah, const __nv_bfloat16* __restrict__ Al,
              const __nv_bfloat16* __restrict__ Bh, const __nv_bfloat16* __restrict__ Bl,
              float* __restrict__ Cout) {
    extern __shared__ char smem[];
    const uint32_t sb = su32(smem);
    const int tid = threadIdx.x;
    const int lane = tid & 31;
    const int wid = tid >> 5;
    const int warpM = wid & 1;
    const int warpN = wid >> 1;
    const int MBase = blockIdx.y * 128;
    const int NBase = blockIdx.x * 128;
    const int v = blockIdx.z;

    if (MODE == 1) { Bh += (size_t)v * WMAT; Bl += (size_t)v * WMAT; }

    // ---- load geometry: thread owns one 128B smem row (pair: 0=A,1=B) ----
    const int pair = tid & 1;
    const int lr = tid >> 1;               // tile row 0..127
    const char* hiPtr;
    const char* loPtr;
    if (pair == 0) {
        int ga;
        if (MODE == 1) {
            int bn = MBase + lr;
            int b = bn / Nn, n = bn - b * Nn;
            ga = (b * Vv + v) * Nn + n;
        } else {
            ga = MBase + lr;
        }
        hiPtr = (const char*)(Ah + (size_t)ga * Cc);
        loPtr = (const char*)(Al + (size_t)ga * Cc);
    } else {
        hiPtr = (const char*)(Bh + (size_t)(NBase + lr) * Cc);
        loPtr = (const char*)(Bl + (size_t)(NBase + lr) * Cc);
    }
    uint32_t so[8];
#pragma unroll
    for (int j = 0; j < 8; j++)
        so[j] = (uint32_t)(lr * 128 + ((j * 16) ^ ((lr & 7) << 4)));
    const uint32_t tileBase = sb + (pair ? OFF_B : 0);

    auto issue = [&](int chunk, int stg) {
        uint32_t base = tileBase + stg * STAGE_BYTES;
        const char* ph = hiPtr + chunk * 64;
        const char* pl = loPtr + chunk * 64;
#pragma unroll
        for (int j = 0; j < 4; j++) cpa16(base + so[j], ph + j * 16);
#pragma unroll
        for (int j = 0; j < 4; j++) cpa16(base + so[4 + j], pl + j * 16);
        cp_commit();
    };

    float acc[4][4][4];
#pragma unroll
    for (int mt = 0; mt < 4; mt++)
#pragma unroll
        for (int nt = 0; nt < 4; nt++)
#pragma unroll
            for (int e = 0; e < 4; e++) acc[mt][nt][e] = 0.f;

    const uint32_t swz = (uint32_t)((lane & 7) << 4);
    const uint32_t aRow0 = (uint32_t)(warpM * 64 + (lane & 15));
    const uint32_t nRow0 = (uint32_t)(warpN * 32 + (lane & 15));
    const uint32_t halfSel = (uint32_t)((lane >> 4) << 4);   // 0 or 16 bytes

    issue(0, 0);
    issue(1, 1);
#pragma unroll 1
    for (int i = 0; i < NCHUNK; i++) {
        if (i < NCHUNK - 1) asm volatile("cp.async.wait_group 1;" ::: "memory");
        else                asm volatile("cp.async.wait_group 0;" ::: "memory");
        __syncthreads();
        if (i + 2 < NCHUNK) issue(i + 2, (i + 2) % NSTAGE);

        uint32_t base = sb + (i % NSTAGE) * STAGE_BYTES;
#pragma unroll
        for (int k16 = 0; k16 < 2; k16++) {
            const uint32_t cHi = (uint32_t)(k16 * 32) + halfSel;
            const uint32_t cLo = cHi + 64;
            uint32_t ah[4][4], al[4][4], bh[4][2], bl[4][2];
#pragma unroll
            for (int mt = 0; mt < 4; mt++) {
                uint32_t rb = base + (aRow0 + mt * 16) * 128;
                ldsm4(ah[mt][0], ah[mt][1], ah[mt][2], ah[mt][3], rb + (cHi ^ swz));
                ldsm4(al[mt][0], al[mt][1], al[mt][2], al[mt][3], rb + (cLo ^ swz));
            }
#pragma unroll
            for (int g = 0; g < 2; g++) {
                uint32_t rb = base + OFF_B + (nRow0 + g * 16) * 128;
                uint32_t r0, r1, r2, r3;
                ldsm4(r0, r1, r2, r3, rb + (cHi ^ swz));
                bh[g * 2 + 0][0] = r0; bh[g * 2 + 0][1] = r2;
                bh[g * 2 + 1][0] = r1; bh[g * 2 + 1][1] = r3;
                ldsm4(r0, r1, r2, r3, rb + (cLo ^ swz));
                bl[g * 2 + 0][0] = r0; bl[g * 2 + 0][1] = r2;
                bl[g * 2 + 1][0] = r1; bl[g * 2 + 1][1] = r3;
            }
#pragma unroll
            for (int mt = 0; mt < 4; mt++)
#pragma unroll
                for (int nt = 0; nt < 4; nt++) {
                    mma16816(acc[mt][nt], ah[mt], bh[nt]);
                    mma16816(acc[mt][nt], ah[mt], bl[nt]);
                    mma16816(acc[mt][nt], al[mt], bh[nt]);
                }
        }
    }

    // ---- epilogue ----
    int grow[8];
#pragma unroll
    for (int mt = 0; mt < 4; mt++) {
#pragma unroll
        for (int h = 0; h < 2; h++) {
            int m = MBase + warpM * 64 + mt * 16 + (lane >> 2) + h * 8;
            if (MODE == 1) {
                int b = m / Nn, n = m - b * Nn;
                grow[mt * 2 + h] = (b * Vv + v) * Nn + n;
            } else {
                grow[mt * 2 + h] = m;
            }
        }
    }
    const int ncol0 = NBase + warpN * 32 + (lane & 3) * 2;
#pragma unroll
    for (int mt = 0; mt < 4; mt++)
#pragma unroll
        for (int nt = 0; nt < 4; nt++) {
            float* p0 = Cout + (size_t)grow[mt * 2 + 0] * Cc + ncol0 + nt * 8;
            float* p1 = Cout + (size_t)grow[mt * 2 + 1] * Cc + ncol0 + nt * 8;
            p0[0] = acc[mt][nt][0]; p0[1] = acc[mt][nt][1];
            p1[0] = acc[mt][nt][2]; p1[1] = acc[mt][nt][3];
        }
}

// ---------------------------------------------------------------------------
// Score: one warp per (b,v,n) row. s = dot(tanh(XW1+CW1+b1), w2) + b2
// ---------------------------------------------------------------------------
__global__ void score_kernel(const float* __restrict__ XW1, const float* __restrict__ CW1,
                             const float* __restrict__ b1, const float* __restrict__ w2,
                             const float* __restrict__ b2, float* __restrict__ S) {
    int gwarp = (blockIdx.x * blockDim.x + threadIdx.x) >> 5;
    int lane = threadIdx.x & 31;
    if (gwarp >= BVN) return;
    int b = gwarp / (Vv * Nn);
    int rem = gwarp % (Vv * Nn);
    int n = rem % Nn;
    const float* xr = XW1 + (size_t)gwarp * Hh;
    const float* cr = CW1 + (size_t)(b * Nn + n) * Hh;
    float sum = 0.f;
#pragma unroll
    for (int h = lane * 4; h < Hh; h += 128) {
        float4 xv = *(const float4*)(xr + h);
        float4 cv = *(const float4*)(cr + h);
        float4 bb = *(const float4*)(b1 + h);
        float4 wv = *(const float4*)(w2 + h);
        sum += tanhf(xv.x + cv.x + bb.x) * wv.x;
        sum += tanhf(xv.y + cv.y + bb.y) * wv.y;
        sum += tanhf(xv.z + cv.z + bb.z) * wv.z;
        sum += tanhf(xv.w + cv.w + bb.w) * wv.w;
    }
#pragma unroll
    for (int off = 16; off; off >>= 1) sum += __shfl_xor_sync(0xFFFFFFFFu, sum, off);
    if (lane == 0) S[gwarp] = sum + b2[0];
}

// ---------------------------------------------------------------------------
// Softmax over views + weighted-sum update.
// Non-last iters: write c as bf16 hi/lo. Last iter: write fp32 c + r.
// ---------------------------------------------------------------------------
__global__ void update_kernel(const float* __restrict__ S, const float* __restrict__ P,
                              float* __restrict__ OutC, float* __restrict__ Rout, int last) {
    int bn = blockIdx.x;
    int b = bn / Nn, n = bn % Nn;
    float sv[Vv];
    float mx = -1e30f;
#pragma unroll
    for (int v = 0; v < Vv; v++) {
        sv[v] = S[(size_t)(b * Vv + v) * Nn + n];
        mx = fmaxf(mx, sv[v]);
    }
    float den = 0.f;
#pragma unroll
    for (int v = 0; v < Vv; v++) { sv[v] = expf(sv[v] - mx); den += sv[v]; }
    float inv = 1.0f / den;
#pragma unroll
    for (int v = 0; v < Vv; v++) sv[v] *= inv;

    int ch = threadIdx.x * 4;
    float4 acc = make_float4(0.f, 0.f, 0.f, 0.f);
#pragma unroll
    for (int v = 0; v < Vv; v++) {
        const float4 pv = *(const float4*)(P + ((size_t)((b * Vv + v) * Nn + n)) * Cc + ch);
        acc.x += sv[v] * pv.x; acc.y += sv[v] * pv.y;
        acc.z += sv[v] * pv.z; acc.w += sv[v] * pv.w;
    }
    if (last) {
        *(float4*)(OutC + (size_t)bn * Cc + ch) = acc;
        if (threadIdx.x == 0) {
            float ent = 0.f;
#pragma unroll
            for (int v = 0; v < Vv; v++) ent -= sv[v] * logf(sv[v] + 1e-8f);
            Rout[bn] = 1.0f - ent / logf((float)Vv);
        }
    } else {
        union { uint16_t u[4]; uint2 p; } hh, ll;
        split1(acc.x, hh.u[0], ll.u[0]);
        split1(acc.y, hh.u[1], ll.u[1]);
        split1(acc.z, hh.u[2], ll.u[2]);
        split1(acc.w, hh.u[3], ll.u[3]);
        size_t o = (size_t)bn * Cc + ch;
        *(uint2*)(g_ch + o) = hh.p;
        *(uint2*)(g_cl + o) = ll.p;
    }
}

// ---------------------------------------------------------------------------
// Launch
// ---------------------------------------------------------------------------
extern "C" void kernel_launch(void* const* d_in, const int* in_sizes, int n_in,
                              void* d_out, int out_size) {
    const float* x       = (const float*)d_in[0];
    const float* w_views = (const float*)d_in[1];
    const float* w1      = (const float*)d_in[2];
    const float* b1      = (const float*)d_in[3];
    const float* w2      = (const float*)d_in[4];
    const float* b2      = (const float*)d_in[5];
    float* out = (float*)d_out;   // c [B,N,C] then r [B,N]

    float *P, *XW1, *CW1, *S;
    __nv_bfloat16 *xh, *xl, *ch, *cl, *Wh, *Wl;
    cudaGetSymbolAddress((void**)&P,   g_P);
    cudaGetSymbolAddress((void**)&XW1, g_XW1);
    cudaGetSymbolAddress((void**)&CW1, g_CW1);
    cudaGetSymbolAddress((void**)&S,   g_S);
    cudaGetSymbolAddress((void**)&xh,  g_xh);
    cudaGetSymbolAddress((void**)&xl,  g_xl);
    cudaGetSymbolAddress((void**)&ch,  g_ch);
    cudaGetSymbolAddress((void**)&cl,  g_cl);
    cudaGetSymbolAddress((void**)&Wh,  g_Wh);
    cudaGetSymbolAddress((void**)&Wl,  g_Wl);

    cudaFuncSetAttribute(mma_gemm<0>, cudaFuncAttributeMaxDynamicSharedMemorySize, SMEM_TOTAL);
    cudaFuncSetAttribute(mma_gemm<1>, cudaFuncAttributeMaxDynamicSharedMemorySize, SMEM_TOTAL);

    // conversions
    {
        size_t tot = (size_t)BVN * Cc / 4;
        split_x_kernel<<<(unsigned)((tot + 255) / 256), 256>>>(x);
        size_t tw = (size_t)7 * WMAT;
        split_w_kernel<<<(unsigned)((tw + 255) / 256), 256>>>(w_views, w1);
        int tm = BN_ROWS * (Cc / 4);
        mean_kernel<<<(tm + 255) / 256, 256>>>(x);
    }
    // proj_x = x @ w_views (per view)
    {
        dim3 grid(Cc / 128, BN_ROWS / 128, Vv);   // (6, 49, 5)
        mma_gemm<1><<<grid, 256, SMEM_TOTAL>>>(xh, xl, Wh, Wl, P);
    }
    // XW1 = x @ w1[:C]
    {
        dim3 grid(Hh / 128, BVN / 128, 1);        // (6, 245)
        mma_gemm<0><<<grid, 256, SMEM_TOTAL>>>(xh, xl, Wh + (size_t)5 * WMAT, Wl + (size_t)5 * WMAT, XW1);
    }
    // iterations
    for (int it = 0; it < NUM_ITERS; it++) {
        dim3 gridc(Hh / 128, BN_ROWS / 128, 1);   // (6, 49)
        mma_gemm<0><<<gridc, 256, SMEM_TOTAL>>>(ch, cl, Wh + (size_t)6 * WMAT, Wl + (size_t)6 * WMAT, CW1);

        int blocks = (BVN * 32 + 255) / 256;
        score_kernel<<<blocks, 256>>>(XW1, CW1, b1, w2, b2, S);

        int last = (it == NUM_ITERS - 1) ? 1 : 0;
        float* rdst = out + (size_t)BN_ROWS * Cc;
        update_kernel<<<BN_ROWS, 192>>>(S, P, out, rdst, last);
    }
    (void)in_sizes; (void)n_in; (void)out_size;
}

// round 5
// speedup vs baseline: 1.0301x; 1.0301x over previous
#include <cuda_runtime.h>
#include <cuda_bf16.h>
#include <cstdint>

#define Bb 32
#define Vv 5
#define Nn 196
#define Cc 768
#define Hh 768
#define BN_ROWS 6272            // Bb*Nn
#define BVN 31360               // Bb*Vv*Nn
#define NUM_ITERS 3
#define WMAT (Cc*Cc)            // 589824

// ---------------------------------------------------------------------------
// Scratch (device globals; no runtime allocation allowed)
// ---------------------------------------------------------------------------
__device__ float g_P[(size_t)BVN * Cc];        // proj_x   fp32
__device__ float g_XW1[(size_t)BVN * Hh];      // x @ w1[:C]
__device__ float g_CW1[(size_t)BN_ROWS * Hh];  // c @ w1[C:]
__device__ float g_S[BVN];                     // scores
__device__ __nv_bfloat16 g_xh[(size_t)BVN * Cc];
__device__ __nv_bfloat16 g_xl[(size_t)BVN * Cc];
__device__ __nv_bfloat16 g_ch[(size_t)BN_ROWS * Cc];
__device__ __nv_bfloat16 g_cl[(size_t)BN_ROWS * Cc];
// 7 transposed [N,K] weight matrices: views 0..4, w1a=5, w1b=6
__device__ __nv_bfloat16 g_Wh[(size_t)7 * WMAT];
__device__ __nv_bfloat16 g_Wl[(size_t)7 * WMAT];

// ---------------------------------------------------------------------------
// Helpers
// ---------------------------------------------------------------------------
__device__ __forceinline__ uint32_t su32(const void* p) {
    uint32_t a;
    asm("{ .reg .u64 t; cvta.to.shared.u64 t, %1; cvt.u32.u64 %0, t; }" : "=r"(a) : "l"(p));
    return a;
}
__device__ __forceinline__ void cpa16(uint32_t d, const void* s) {
    asm volatile("cp.async.cg.shared.global [%0], [%1], 16;" :: "r"(d), "l"(s) : "memory");
}
__device__ __forceinline__ void cp_commit() {
    asm volatile("cp.async.commit_group;" ::: "memory");
}
__device__ __forceinline__ void ldsm4(uint32_t& r0, uint32_t& r1, uint32_t& r2, uint32_t& r3,
                                      uint32_t addr) {
    asm volatile("ldmatrix.sync.aligned.m8n8.x4.shared.b16 {%0,%1,%2,%3}, [%4];"
                 : "=r"(r0), "=r"(r1), "=r"(r2), "=r"(r3) : "r"(addr));
}
__device__ __forceinline__ void mma16816(float* d, const uint32_t* a, const uint32_t* b) {
    asm volatile(
        "mma.sync.aligned.m16n8k16.row.col.f32.bf16.bf16.f32 "
        "{%0,%1,%2,%3}, {%4,%5,%6,%7}, {%8,%9}, {%0,%1,%2,%3};"
        : "+f"(d[0]), "+f"(d[1]), "+f"(d[2]), "+f"(d[3])
        : "r"(a[0]), "r"(a[1]), "r"(a[2]), "r"(a[3]), "r"(b[0]), "r"(b[1]));
}

__device__ __forceinline__ void split1(float a, uint16_t& h, uint16_t& l) {
    __nv_bfloat16 bh = __float2bfloat16(a);
    __nv_bfloat16 bl = __float2bfloat16(a - __bfloat162float(bh));
    h = *(uint16_t*)&bh;
    l = *(uint16_t*)&bl;
}

// ---------------------------------------------------------------------------
// Split x into bf16 hi/lo
// ---------------------------------------------------------------------------
__global__ void split_x_kernel(const float* __restrict__ x) {
    size_t i = (size_t)blockIdx.x * blockDim.x + threadIdx.x;
    const size_t TOT = (size_t)BVN * Cc / 4;
    if (i >= TOT) return;
    float4 v = *(const float4*)(x + i * 4);
    union { uint16_t u[4]; uint2 p; } hh, ll;
    split1(v.x, hh.u[0], ll.u[0]);
    split1(v.y, hh.u[1], ll.u[1]);
    split1(v.z, hh.u[2], ll.u[2]);
    split1(v.w, hh.u[3], ll.u[3]);
    *(uint2*)(g_xh + i * 4) = hh.p;
    *(uint2*)(g_xl + i * 4) = ll.p;
}

// ---------------------------------------------------------------------------
// Transpose + split weights into g_Wh/g_Wl ([N,K] K-major, 7 matrices)
// ---------------------------------------------------------------------------
__global__ void split_w_kernel(const float* __restrict__ w_views, const float* __restrict__ w1) {
    size_t j = (size_t)blockIdx.x * blockDim.x + threadIdx.x;
    const size_t TOT = (size_t)7 * WMAT;
    if (j >= TOT) return;
    int m = (int)(j / WMAT);
    int r = (int)(j % WMAT);
    int n = r / Cc, k = r % Cc;
    float s;
    if (m < 5)       s = w_views[(size_t)m * WMAT + (size_t)k * Cc + n];
    else if (m == 5) s = w1[(size_t)k * Hh + n];
    else             s = w1[(size_t)(Cc + k) * Hh + n];
    uint16_t h, l;
    split1(s, h, l);
    *(uint16_t*)(g_Wh + j) = h;
    *(uint16_t*)(g_Wl + j) = l;
}

// ---------------------------------------------------------------------------
// Mean over views -> c0 as bf16 hi/lo
// ---------------------------------------------------------------------------
__global__ void mean_kernel(const float* __restrict__ x) {
    int i = blockIdx.x * blockDim.x + threadIdx.x;
    const int TOT = BN_ROWS * (Cc / 4);
    if (i >= TOT) return;
    int bn = i / (Cc / 4);
    int cq = (i % (Cc / 4)) * 4;
    int b = bn / Nn, n = bn % Nn;
    float4 acc = make_float4(0.f, 0.f, 0.f, 0.f);
#pragma unroll
    for (int v = 0; v < Vv; v++) {
        const float4 xv = *(const float4*)(x + ((size_t)((b * Vv + v) * Nn + n)) * Cc + cq);
        acc.x += xv.x; acc.y += xv.y; acc.z += xv.z; acc.w += xv.w;
    }
    const float s = 1.0f / Vv;
    acc.x *= s; acc.y *= s; acc.z *= s; acc.w *= s;
    union { uint16_t u[4]; uint2 p; } hh, ll;
    split1(acc.x, hh.u[0], ll.u[0]);
    split1(acc.y, hh.u[1], ll.u[1]);
    split1(acc.z, hh.u[2], ll.u[2]);
    split1(acc.w, hh.u[3], ll.u[3]);
    size_t o = (size_t)bn * Cc + cq;
    *(uint2*)(g_ch + o) = hh.p;
    *(uint2*)(g_cl + o) = ll.p;
}

// ---------------------------------------------------------------------------
// mma.sync bf16x3 GEMM: CTA tile 128x256, warp tile 64x64 (8 warps, 2M x 4N).
// K=768 in 12 chunks of 64. Stage 96KB: Ah(16K) Al(16K) Bh(32K) Bl(32K),
// combined 768 rows of 128B. Double-buffered cp.async (192KB smem, 1 CTA/SM).
// MODE 0: flat rows. MODE 1: per-view gather/scatter (v = blockIdx.z).
// ---------------------------------------------------------------------------
#define STAGE_BYTES 98304
#define SMEM_TOTAL  (2 * STAGE_BYTES)
#define OFF_AL 16384
#define OFF_BH 32768
#define OFF_BL 65536
#define NCHUNK 12

template <int MODE>
__global__ __launch_bounds__(256, 1)
void mma_gemm(const __nv_bfloat16* __restrict__ Ah, const __nv_bfloat16* __restrict__ Al,
              const __nv_bfloat16* __restrict__ Bh, const __nv_bfloat16* __restrict__ Bl,
              float* __restrict__ Cout) {
    extern __shared__ char smem[];
    const uint32_t sb = su32(smem);
    const int tid = threadIdx.x;
    const int lane = tid & 31;
    const int wid = tid >> 5;
    const int warpM = wid & 1;
    const int warpN = wid >> 1;
    const int MBase = blockIdx.y * 128;
    const int NBase = blockIdx.x * 256;
    const int v = blockIdx.z;

    if (MODE == 1) { Bh += (size_t)v * WMAT; Bl += (size_t)v * WMAT; }

    // ---- load geometry: each thread owns 3 of the 768 combined 128B rows ----
    // rows [0,128): Ah  [128,256): Al  [256,512): Bh  [512,768): Bl
    const int arow = tid & 127;            // A tile row for this thread
    int ga;
    if (MODE == 1) {
        int bn = MBase + arow;
        int b = bn / Nn, n = bn - b * Nn;
        ga = (b * Vv + v) * Nn + n;
    } else {
        ga = MBase + arow;
    }
    const char* srcA = (const char*)((tid < 128 ? Ah : Al) + (size_t)ga * Cc);
    const char* srcBh = (const char*)(Bh + (size_t)(NBase + tid) * Cc);
    const char* srcBl = (const char*)(Bl + (size_t)(NBase + tid) * Cc);
    const uint32_t rowA  = (uint32_t)tid * 128;            // rows 0..255 (Ah|Al)
    const uint32_t rowBh = (uint32_t)(tid + 256) * 128;
    const uint32_t rowBl = (uint32_t)(tid + 512) * 128;
    uint32_t so[8];
#pragma unroll
    for (int j = 0; j < 8; j++)
        so[j] = (uint32_t)((j * 16) ^ ((tid & 7) << 4));

    auto issue = [&](int chunk, int stg) {
        uint32_t base = sb + stg * STAGE_BYTES;
        const char* pA  = srcA  + chunk * 128;
        const char* pBh = srcBh + chunk * 128;
        const char* pBl = srcBl + chunk * 128;
#pragma unroll
        for (int j = 0; j < 8; j++) cpa16(base + rowA + so[j], pA + j * 16);
#pragma unroll
        for (int j = 0; j < 8; j++) cpa16(base + rowBh + so[j], pBh + j * 16);
#pragma unroll
        for (int j = 0; j < 8; j++) cpa16(base + rowBl + so[j], pBl + j * 16);
        cp_commit();
    };

    float acc[4][8][4];
#pragma unroll
    for (int mt = 0; mt < 4; mt++)
#pragma unroll
        for (int nt = 0; nt < 8; nt++)
#pragma unroll
            for (int e = 0; e < 4; e++) acc[mt][nt][e] = 0.f;

    const uint32_t swz = (uint32_t)((lane & 7) << 4);
    const uint32_t aRow0 = (uint32_t)(warpM * 64 + (lane & 15));
    const uint32_t nRow0 = (uint32_t)(warpN * 64 + (lane & 15));
    const uint32_t halfSel = (uint32_t)((lane >> 4) << 4);   // 0 or 16 bytes

    issue(0, 0);
#pragma unroll 1
    for (int i = 0; i < NCHUNK; i++) {
        int stg = i & 1;
        if (i + 1 < NCHUNK) {
            issue(i + 1, stg ^ 1);
            asm volatile("cp.async.wait_group 1;" ::: "memory");
        } else {
            asm volatile("cp.async.wait_group 0;" ::: "memory");
        }
        __syncthreads();

        uint32_t base = sb + stg * STAGE_BYTES;
#pragma unroll
        for (int k16 = 0; k16 < 4; k16++) {
            const uint32_t bc = (uint32_t)(k16 * 32) + halfSel;
            uint32_t ah[4][4], al[4][4], bh[8][2], bl[8][2];
#pragma unroll
            for (int mt = 0; mt < 4; mt++) {
                uint32_t ad = base + (aRow0 + mt * 16) * 128 + (bc ^ swz);
                ldsm4(ah[mt][0], ah[mt][1], ah[mt][2], ah[mt][3], ad);
                ldsm4(al[mt][0], al[mt][1], al[mt][2], al[mt][3], ad + OFF_AL);
            }
#pragma unroll
            for (int g = 0; g < 4; g++) {
                uint32_t ad = base + OFF_BH + (nRow0 + g * 16) * 128 + (bc ^ swz);
                uint32_t r0, r1, r2, r3;
                ldsm4(r0, r1, r2, r3, ad);
                bh[g * 2 + 0][0] = r0; bh[g * 2 + 0][1] = r2;
                bh[g * 2 + 1][0] = r1; bh[g * 2 + 1][1] = r3;
                ldsm4(r0, r1, r2, r3, ad + (OFF_BL - OFF_BH));
                bl[g * 2 + 0][0] = r0; bl[g * 2 + 0][1] = r2;
                bl[g * 2 + 1][0] = r1; bl[g * 2 + 1][1] = r3;
            }
#pragma unroll
            for (int mt = 0; mt < 4; mt++)
#pragma unroll
                for (int nt = 0; nt < 8; nt++) {
                    mma16816(acc[mt][nt], ah[mt], bh[nt]);
                    mma16816(acc[mt][nt], ah[mt], bl[nt]);
                    mma16816(acc[mt][nt], al[mt], bh[nt]);
                }
        }
        __syncthreads();
    }

    // ---- epilogue ----
    int grow[8];
#pragma unroll
    for (int mt = 0; mt < 4; mt++) {
#pragma unroll
        for (int h = 0; h < 2; h++) {
            int m = MBase + warpM * 64 + mt * 16 + (lane >> 2) + h * 8;
            if (MODE == 1) {
                int b = m / Nn, n = m - b * Nn;
                grow[mt * 2 + h] = (b * Vv + v) * Nn + n;
            } else {
                grow[mt * 2 + h] = m;
            }
        }
    }
    const int ncol0 = NBase + warpN * 64 + (lane & 3) * 2;
#pragma unroll
    for (int mt = 0; mt < 4; mt++)
#pragma unroll
        for (int nt = 0; nt < 8; nt++) {
            float* p0 = Cout + (size_t)grow[mt * 2 + 0] * Cc + ncol0 + nt * 8;
            float* p1 = Cout + (size_t)grow[mt * 2 + 1] * Cc + ncol0 + nt * 8;
            p0[0] = acc[mt][nt][0]; p0[1] = acc[mt][nt][1];
            p1[0] = acc[mt][nt][2]; p1[1] = acc[mt][nt][3];
        }
}

// ---------------------------------------------------------------------------
// Score: one warp per (b,v,n) row. s = dot(tanh(XW1+CW1+b1), w2) + b2
// ---------------------------------------------------------------------------
__global__ void score_kernel(const float* __restrict__ XW1, const float* __restrict__ CW1,
                             const float* __restrict__ b1, const float* __restrict__ w2,
                             const float* __restrict__ b2, float* __restrict__ S) {
    int gwarp = (blockIdx.x * blockDim.x + threadIdx.x) >> 5;
    int lane = threadIdx.x & 31;
    if (gwarp >= BVN) return;
    int b = gwarp / (Vv * Nn);
    int rem = gwarp % (Vv * Nn);
    int n = rem % Nn;
    const float* xr = XW1 + (size_t)gwarp * Hh;
    const float* cr = CW1 + (size_t)(b * Nn + n) * Hh;
    float sum = 0.f;
#pragma unroll
    for (int h = lane * 4; h < Hh; h += 128) {
        float4 xv = *(const float4*)(xr + h);
        float4 cv = *(const float4*)(cr + h);
        float4 bb = *(const float4*)(b1 + h);
        float4 wv = *(const float4*)(w2 + h);
        sum += tanhf(xv.x + cv.x + bb.x) * wv.x;
        sum += tanhf(xv.y + cv.y + bb.y) * wv.y;
        sum += tanhf(xv.z + cv.z + bb.z) * wv.z;
        sum += tanhf(xv.w + cv.w + bb.w) * wv.w;
    }
#pragma unroll
    for (int off = 16; off; off >>= 1) sum += __shfl_xor_sync(0xFFFFFFFFu, sum, off);
    if (lane == 0) S[gwarp] = sum + b2[0];
}

// ---------------------------------------------------------------------------
// Softmax over views + weighted-sum update.
// Non-last iters: write c as bf16 hi/lo. Last iter: write fp32 c + r.
// ---------------------------------------------------------------------------
__global__ void update_kernel(const float* __restrict__ S, const float* __restrict__ P,
                              float* __restrict__ OutC, float* __restrict__ Rout, int last) {
    int bn = blockIdx.x;
    int b = bn / Nn, n = bn % Nn;
    float sv[Vv];
    float mx = -1e30f;
#pragma unroll
    for (int v = 0; v < Vv; v++) {
        sv[v] = S[(size_t)(b * Vv + v) * Nn + n];
        mx = fmaxf(mx, sv[v]);
    }
    float den = 0.f;
#pragma unroll
    for (int v = 0; v < Vv; v++) { sv[v] = expf(sv[v] - mx); den += sv[v]; }
    float inv = 1.0f / den;
#pragma unroll
    for (int v = 0; v < Vv; v++) sv[v] *= inv;

    int ch = threadIdx.x * 4;
    float4 acc = make_float4(0.f, 0.f, 0.f, 0.f);
#pragma unroll
    for (int v = 0; v < Vv; v++) {
        const float4 pv = *(const float4*)(P + ((size_t)((b * Vv + v) * Nn + n)) * Cc + ch);
        acc.x += sv[v] * pv.x; acc.y += sv[v] * pv.y;
        acc.z += sv[v] * pv.z; acc.w += sv[v] * pv.w;
    }
    if (last) {
        *(float4*)(OutC + (size_t)bn * Cc + ch) = acc;
        if (threadIdx.x == 0) {
            float ent = 0.f;
#pragma unroll
            for (int v = 0; v < Vv; v++) ent -= sv[v] * logf(sv[v] + 1e-8f);
            Rout[bn] = 1.0f - ent / logf((float)Vv);
        }
    } else {
        union { uint16_t u[4]; uint2 p; } hh, ll;
        split1(acc.x, hh.u[0], ll.u[0]);
        split1(acc.y, hh.u[1], ll.u[1]);
        split1(acc.z, hh.u[2], ll.u[2]);
        split1(acc.w, hh.u[3], ll.u[3]);
        size_t o = (size_t)bn * Cc + ch;
        *(uint2*)(g_ch + o) = hh.p;
        *(uint2*)(g_cl + o) = ll.p;
    }
}

// ---------------------------------------------------------------------------
// Launch
// ---------------------------------------------------------------------------
extern "C" void kernel_launch(void* const* d_in, const int* in_sizes, int n_in,
                              void* d_out, int out_size) {
    const float* x       = (const float*)d_in[0];
    const float* w_views = (const float*)d_in[1];
    const float* w1      = (const float*)d_in[2];
    const float* b1      = (const float*)d_in[3];
    const float* w2      = (const float*)d_in[4];
    const float* b2      = (const float*)d_in[5];
    float* out = (float*)d_out;   // c [B,N,C] then r [B,N]

    float *P, *XW1, *CW1, *S;
    __nv_bfloat16 *xh, *xl, *ch, *cl, *Wh, *Wl;
    cudaGetSymbolAddress((void**)&P,   g_P);
    cudaGetSymbolAddress((void**)&XW1, g_XW1);
    cudaGetSymbolAddress((void**)&CW1, g_CW1);
    cudaGetSymbolAddress((void**)&S,   g_S);
    cudaGetSymbolAddress((void**)&xh,  g_xh);
    cudaGetSymbolAddress((void**)&xl,  g_xl);
    cudaGetSymbolAddress((void**)&ch,  g_ch);
    cudaGetSymbolAddress((void**)&cl,  g_cl);
    cudaGetSymbolAddress((void**)&Wh,  g_Wh);
    cudaGetSymbolAddress((void**)&Wl,  g_Wl);

    cudaFuncSetAttribute(mma_gemm<0>, cudaFuncAttributeMaxDynamicSharedMemorySize, SMEM_TOTAL);
    cudaFuncSetAttribute(mma_gemm<1>, cudaFuncAttributeMaxDynamicSharedMemorySize, SMEM_TOTAL);

    // conversions
    {
        size_t tot = (size_t)BVN * Cc / 4;
        split_x_kernel<<<(unsigned)((tot + 255) / 256), 256>>>(x);
        size_t tw = (size_t)7 * WMAT;
        split_w_kernel<<<(unsigned)((tw + 255) / 256), 256>>>(w_views, w1);
        int tm = BN_ROWS * (Cc / 4);
        mean_kernel<<<(tm + 255) / 256, 256>>>(x);
    }
    // proj_x = x @ w_views (per view)
    {
        dim3 grid(Cc / 256, BN_ROWS / 128, Vv);   // (3, 49, 5)
        mma_gemm<1><<<grid, 256, SMEM_TOTAL>>>(xh, xl, Wh, Wl, P);
    }
    // XW1 = x @ w1[:C]
    {
        dim3 grid(Hh / 256, BVN / 128, 1);        // (3, 245)
        mma_gemm<0><<<grid, 256, SMEM_TOTAL>>>(xh, xl, Wh + (size_t)5 * WMAT, Wl + (size_t)5 * WMAT, XW1);
    }
    // iterations
    for (int it = 0; it < NUM_ITERS; it++) {
        dim3 gridc(Hh / 256, BN_ROWS / 128, 1);   // (3, 49)
        mma_gemm<0><<<gridc, 256, SMEM_TOTAL>>>(ch, cl, Wh + (size_t)6 * WMAT, Wl + (size_t)6 * WMAT, CW1);

        int blocks = (BVN * 32 + 255) / 256;
        score_kernel<<<blocks, 256>>>(XW1, CW1, b1, w2, b2, S);

        int last = (it == NUM_ITERS - 1) ? 1 : 0;
        float* rdst = out + (size_t)BN_ROWS * Cc;
        update_kernel<<<BN_ROWS, 192>>>(S, P, out, rdst, last);
    }
    (void)in_sizes; (void)n_in; (void)out_size;
}

// round 6
// speedup vs baseline: 1.1468x; 1.1133x over previous
#include <cuda_runtime.h>
#include <cuda_bf16.h>
#include <cstdint>

#define Bb 32
#define Vv 5
#define Nn 196
#define Cc 768
#define Hh 768
#define BN_ROWS 6272            // Bb*Nn
#define BVN 31360               // Bb*Vv*Nn
#define NUM_ITERS 3
#define WMAT (Cc*Cc)            // 589824

// ---------------------------------------------------------------------------
// Scratch (device globals; no runtime allocation allowed)
// ---------------------------------------------------------------------------
__device__ float g_P[(size_t)BVN * Cc];        // proj_x   fp32
__device__ float g_XW1[(size_t)BVN * Hh];      // x @ w1[:C]
__device__ float g_CW1[(size_t)BN_ROWS * Hh];  // c @ w1[C:]
__device__ float g_S[BVN];                     // scores
__device__ __nv_bfloat16 g_xh[(size_t)BVN * Cc];
__device__ __nv_bfloat16 g_xl[(size_t)BVN * Cc];
__device__ __nv_bfloat16 g_ch[(size_t)BN_ROWS * Cc];
__device__ __nv_bfloat16 g_cl[(size_t)BN_ROWS * Cc];
// 7 transposed [N,K] weight matrices: views 0..4, w1a=5, w1b=6
__device__ __nv_bfloat16 g_Wh[(size_t)7 * WMAT];
__device__ __nv_bfloat16 g_Wl[(size_t)7 * WMAT];

// ---------------------------------------------------------------------------
// Helpers
// ---------------------------------------------------------------------------
__device__ __forceinline__ uint32_t su32(const void* p) {
    uint32_t a;
    asm("{ .reg .u64 t; cvta.to.shared.u64 t, %1; cvt.u32.u64 %0, t; }" : "=r"(a) : "l"(p));
    return a;
}
__device__ __forceinline__ void cpa16(uint32_t d, const void* s) {
    asm volatile("cp.async.cg.shared.global [%0], [%1], 16;" :: "r"(d), "l"(s) : "memory");
}
__device__ __forceinline__ void cp_commit() {
    asm volatile("cp.async.commit_group;" ::: "memory");
}
__device__ __forceinline__ void ldsm4(uint32_t& r0, uint32_t& r1, uint32_t& r2, uint32_t& r3,
                                      uint32_t addr) {
    asm volatile("ldmatrix.sync.aligned.m8n8.x4.shared.b16 {%0,%1,%2,%3}, [%4];"
                 : "=r"(r0), "=r"(r1), "=r"(r2), "=r"(r3) : "r"(addr));
}
__device__ __forceinline__ void mma16816(float* d, const uint32_t* a, const uint32_t* b) {
    asm volatile(
        "mma.sync.aligned.m16n8k16.row.col.f32.bf16.bf16.f32 "
        "{%0,%1,%2,%3}, {%4,%5,%6,%7}, {%8,%9}, {%0,%1,%2,%3};"
        : "+f"(d[0]), "+f"(d[1]), "+f"(d[2]), "+f"(d[3])
        : "r"(a[0]), "r"(a[1]), "r"(a[2]), "r"(a[3]), "r"(b[0]), "r"(b[1]));
}

__device__ __forceinline__ void split1(float a, uint16_t& h, uint16_t& l) {
    __nv_bfloat16 bh = __float2bfloat16(a);
    __nv_bfloat16 bl = __float2bfloat16(a - __bfloat162float(bh));
    h = *(uint16_t*)&bh;
    l = *(uint16_t*)&bl;
}

// ---------------------------------------------------------------------------
// Split x into bf16 hi/lo
// ---------------------------------------------------------------------------
__global__ void split_x_kernel(const float* __restrict__ x) {
    size_t i = (size_t)blockIdx.x * blockDim.x + threadIdx.x;
    const size_t TOT = (size_t)BVN * Cc / 4;
    if (i >= TOT) return;
    float4 v = *(const float4*)(x + i * 4);
    union { uint16_t u[4]; uint2 p; } hh, ll;
    split1(v.x, hh.u[0], ll.u[0]);
    split1(v.y, hh.u[1], ll.u[1]);
    split1(v.z, hh.u[2], ll.u[2]);
    split1(v.w, hh.u[3], ll.u[3]);
    *(uint2*)(g_xh + i * 4) = hh.p;
    *(uint2*)(g_xl + i * 4) = ll.p;
}

// ---------------------------------------------------------------------------
// Transpose + split weights into g_Wh/g_Wl ([N,K] K-major, 7 matrices)
// ---------------------------------------------------------------------------
__global__ void split_w_kernel(const float* __restrict__ w_views, const float* __restrict__ w1) {
    size_t j = (size_t)blockIdx.x * blockDim.x + threadIdx.x;
    const size_t TOT = (size_t)7 * WMAT;
    if (j >= TOT) return;
    int m = (int)(j / WMAT);
    int r = (int)(j % WMAT);
    int n = r / Cc, k = r % Cc;
    float s;
    if (m < 5)       s = w_views[(size_t)m * WMAT + (size_t)k * Cc + n];
    else if (m == 5) s = w1[(size_t)k * Hh + n];
    else             s = w1[(size_t)(Cc + k) * Hh + n];
    uint16_t h, l;
    split1(s, h, l);
    *(uint16_t*)(g_Wh + j) = h;
    *(uint16_t*)(g_Wl + j) = l;
}

// ---------------------------------------------------------------------------
// Mean over views -> c0 as bf16 hi/lo
// ---------------------------------------------------------------------------
__global__ void mean_kernel(const float* __restrict__ x) {
    int i = blockIdx.x * blockDim.x + threadIdx.x;
    const int TOT = BN_ROWS * (Cc / 4);
    if (i >= TOT) return;
    int bn = i / (Cc / 4);
    int cq = (i % (Cc / 4)) * 4;
    int b = bn / Nn, n = bn % Nn;
    float4 acc = make_float4(0.f, 0.f, 0.f, 0.f);
#pragma unroll
    for (int v = 0; v < Vv; v++) {
        const float4 xv = *(const float4*)(x + ((size_t)((b * Vv + v) * Nn + n)) * Cc + cq);
        acc.x += xv.x; acc.y += xv.y; acc.z += xv.z; acc.w += xv.w;
    }
    const float s = 1.0f / Vv;
    acc.x *= s; acc.y *= s; acc.z *= s; acc.w *= s;
    union { uint16_t u[4]; uint2 p; } hh, ll;
    split1(acc.x, hh.u[0], ll.u[0]);
    split1(acc.y, hh.u[1], ll.u[1]);
    split1(acc.z, hh.u[2], ll.u[2]);
    split1(acc.w, hh.u[3], ll.u[3]);
    size_t o = (size_t)bn * Cc + cq;
    *(uint2*)(g_ch + o) = hh.p;
    *(uint2*)(g_cl + o) = ll.p;
}

// ---------------------------------------------------------------------------
// mma.sync bf16x3 GEMM (round-3 config + register frag double-buffering):
// CTA 128x128, 8 warps (2M x 4N), warp tile 64x32, K=768 in 12 chunks of 64.
// Stage 64KB: Ah/Al/Bh/Bl 16KB each; 2 stages (128KB, 1 CTA/SM).
// Fragments for k16+1 are LDSM'd before k16's MMAs issue -> tensor pipe never
// waits on in-flight LDSM.
// MODE 0: flat rows. MODE 1: per-view gather/scatter (v = blockIdx.z).
// ---------------------------------------------------------------------------
#define STAGE_BYTES 65536          // 4 tiles x 16KB (Ah, Al, Bh, Bl)
#define SMEM_TOTAL  (2 * STAGE_BYTES)
#define OFF_AL 16384
#define OFF_BH 32768
#define OFF_BL 49152
#define NCHUNK 12

template <int MODE>
__global__ __launch_bounds__(256, 1)
void mma_gemm(const __nv_bfloat16* __restrict__ Ah, const __nv_bfloat16* __restrict__ Al,
              const __nv_bfloat16* __restrict__ Bh, const __nv_bfloat16* __restrict__ Bl,
              float* __restrict__ Cout) {
    extern __shared__ char smem[];
    const uint32_t sb = su32(smem);
    const int tid = threadIdx.x;
    const int lane = tid & 31;
    const int wid = tid >> 5;
    const int warpM = wid & 1;
    const int warpN = wid >> 1;
    const int MBase = blockIdx.y * 128;
    const int NBase = blockIdx.x * 128;
    const int v = blockIdx.z;

    if (MODE == 1) { Bh += (size_t)v * WMAT; Bl += (size_t)v * WMAT; }

    // ---- load geometry: each thread owns one tile-row half (64B) ----
    const int lr = tid >> 1;                 // tile row 0..127
    const int lc = (tid & 1) * 64;           // byte offset within 128B row
    int gaRow;
    if (MODE == 1) {
        int bn = MBase + lr;
        int b = bn / Nn, n = bn - b * Nn;
        gaRow = (b * Vv + v) * Nn + n;
    } else {
        gaRow = MBase + lr;
    }
    const char* aRowPtr = (const char*)(Ah + (size_t)gaRow * Cc) + lc;
    const char* bRowPtr = (const char*)(Bh + (size_t)(NBase + lr) * Cc) + lc;
    const ptrdiff_t dAl = (const char*)Al - (const char*)Ah;
    const ptrdiff_t dBl = (const char*)Bl - (const char*)Bh;
    uint32_t so[4];
#pragma unroll
    for (int j = 0; j < 4; j++)
        so[j] = (uint32_t)(lr * 128 + ((lc + j * 16) ^ ((lr & 7) << 4)));

    auto issue = [&](int chunk, int stg) {
        uint32_t base = sb + stg * STAGE_BYTES;
        const char* pa = aRowPtr + chunk * 128;
        const char* pb = bRowPtr + chunk * 128;
#pragma unroll
        for (int j = 0; j < 4; j++) {
            cpa16(base + so[j], pa + j * 16);
            cpa16(base + OFF_AL + so[j], pa + dAl + j * 16);
            cpa16(base + OFF_BH + so[j], pb + j * 16);
            cpa16(base + OFF_BL + so[j], pb + dBl + j * 16);
        }
        cp_commit();
    };

    float acc[4][4][4];
#pragma unroll
    for (int mt = 0; mt < 4; mt++)
#pragma unroll
        for (int nt = 0; nt < 4; nt++)
#pragma unroll
            for (int e = 0; e < 4; e++) acc[mt][nt][e] = 0.f;

    const uint32_t swz = (uint32_t)((lane & 7) << 4);
    const uint32_t aRow0 = (uint32_t)(warpM * 64 + (lane & 15));
    const uint32_t nRow0 = (uint32_t)(warpN * 32 + (lane & 15));
    const uint32_t halfSel = (uint32_t)((lane >> 4) << 4);   // 0 or 16 bytes

    // double-buffered fragments
    uint32_t ah[2][4][4], al[2][4][4], bh[2][4][2], bl[2][4][2];

    auto ldfrags = [&](uint32_t base, int k16, int buf) {
        const uint32_t bc = (uint32_t)(k16 * 32) + halfSel;
#pragma unroll
        for (int mt = 0; mt < 4; mt++) {
            uint32_t ad = base + (aRow0 + mt * 16) * 128 + (bc ^ swz);
            ldsm4(ah[buf][mt][0], ah[buf][mt][1], ah[buf][mt][2], ah[buf][mt][3], ad);
            ldsm4(al[buf][mt][0], al[buf][mt][1], al[buf][mt][2], al[buf][mt][3], ad + OFF_AL);
        }
#pragma unroll
        for (int g = 0; g < 2; g++) {
            uint32_t ad = base + OFF_BH + (nRow0 + g * 16) * 128 + (bc ^ swz);
            uint32_t r0, r1, r2, r3;
            ldsm4(r0, r1, r2, r3, ad);
            bh[buf][g * 2 + 0][0] = r0; bh[buf][g * 2 + 0][1] = r2;
            bh[buf][g * 2 + 1][0] = r1; bh[buf][g * 2 + 1][1] = r3;
            ldsm4(r0, r1, r2, r3, ad + (OFF_BL - OFF_BH));
            bl[buf][g * 2 + 0][0] = r0; bl[buf][g * 2 + 0][1] = r2;
            bl[buf][g * 2 + 1][0] = r1; bl[buf][g * 2 + 1][1] = r3;
        }
    };

    issue(0, 0);
#pragma unroll 1
    for (int i = 0; i < NCHUNK; i++) {
        int stg = i & 1;
        if (i + 1 < NCHUNK) {
            issue(i + 1, stg ^ 1);
            asm volatile("cp.async.wait_group 1;" ::: "memory");
        } else {
            asm volatile("cp.async.wait_group 0;" ::: "memory");
        }
        __syncthreads();

        uint32_t base = sb + stg * STAGE_BYTES;
        ldfrags(base, 0, 0);
#pragma unroll
        for (int k16 = 0; k16 < 4; k16++) {
            const int buf = k16 & 1;
            if (k16 < 3) ldfrags(base, k16 + 1, buf ^ 1);   // prefetch next frags
#pragma unroll
            for (int mt = 0; mt < 4; mt++)
#pragma unroll
                for (int nt = 0; nt < 4; nt++) {
                    mma16816(acc[mt][nt], ah[buf][mt], bh[buf][nt]);
                    mma16816(acc[mt][nt], ah[buf][mt], bl[buf][nt]);
                    mma16816(acc[mt][nt], al[buf][mt], bh[buf][nt]);
                }
        }
        __syncthreads();
    }

    // ---- epilogue ----
    int grow[8];
#pragma unroll
    for (int mt = 0; mt < 4; mt++) {
#pragma unroll
        for (int h = 0; h < 2; h++) {
            int m = MBase + warpM * 64 + mt * 16 + (lane >> 2) + h * 8;
            if (MODE == 1) {
                int b = m / Nn, n = m - b * Nn;
                grow[mt * 2 + h] = (b * Vv + v) * Nn + n;
            } else {
                grow[mt * 2 + h] = m;
            }
        }
    }
    const int ncol0 = NBase + warpN * 32 + (lane & 3) * 2;
#pragma unroll
    for (int mt = 0; mt < 4; mt++)
#pragma unroll
        for (int nt = 0; nt < 4; nt++) {
            float* p0 = Cout + (size_t)grow[mt * 2 + 0] * Cc + ncol0 + nt * 8;
            float* p1 = Cout + (size_t)grow[mt * 2 + 1] * Cc + ncol0 + nt * 8;
            p0[0] = acc[mt][nt][0]; p0[1] = acc[mt][nt][1];
            p1[0] = acc[mt][nt][2]; p1[1] = acc[mt][nt][3];
        }
}

// ---------------------------------------------------------------------------
// Score: one warp per (b,v,n) row. s = dot(tanh(XW1+CW1+b1), w2) + b2
// ---------------------------------------------------------------------------
__global__ void score_kernel(const float* __restrict__ XW1, const float* __restrict__ CW1,
                             const float* __restrict__ b1, const float* __restrict__ w2,
                             const float* __restrict__ b2, float* __restrict__ S) {
    int gwarp = (blockIdx.x * blockDim.x + threadIdx.x) >> 5;
    int lane = threadIdx.x & 31;
    if (gwarp >= BVN) return;
    int b = gwarp / (Vv * Nn);
    int rem = gwarp % (Vv * Nn);
    int n = rem % Nn;
    const float* xr = XW1 + (size_t)gwarp * Hh;
    const float* cr = CW1 + (size_t)(b * Nn + n) * Hh;
    float sum = 0.f;
#pragma unroll
    for (int h = lane * 4; h < Hh; h += 128) {
        float4 xv = *(const float4*)(xr + h);
        float4 cv = *(const float4*)(cr + h);
        float4 bb = *(const float4*)(b1 + h);
        float4 wv = *(const float4*)(w2 + h);
        sum += tanhf(xv.x + cv.x + bb.x) * wv.x;
        sum += tanhf(xv.y + cv.y + bb.y) * wv.y;
        sum += tanhf(xv.z + cv.z + bb.z) * wv.z;
        sum += tanhf(xv.w + cv.w + bb.w) * wv.w;
    }
#pragma unroll
    for (int off = 16; off; off >>= 1) sum += __shfl_xor_sync(0xFFFFFFFFu, sum, off);
    if (lane == 0) S[gwarp] = sum + b2[0];
}

// ---------------------------------------------------------------------------
// Softmax over views + weighted-sum update.
// Non-last iters: write c as bf16 hi/lo. Last iter: write fp32 c + r.
// ---------------------------------------------------------------------------
__global__ void update_kernel(const float* __restrict__ S, const float* __restrict__ P,
                              float* __restrict__ OutC, float* __restrict__ Rout, int last) {
    int bn = blockIdx.x;
    int b = bn / Nn, n = bn % Nn;
    float sv[Vv];
    float mx = -1e30f;
#pragma unroll
    for (int v = 0; v < Vv; v++) {
        sv[v] = S[(size_t)(b * Vv + v) * Nn + n];
        mx = fmaxf(mx, sv[v]);
    }
    float den = 0.f;
#pragma unroll
    for (int v = 0; v < Vv; v++) { sv[v] = expf(sv[v] - mx); den += sv[v]; }
    float inv = 1.0f / den;
#pragma unroll
    for (int v = 0; v < Vv; v++) sv[v] *= inv;

    int ch = threadIdx.x * 4;
    float4 acc = make_float4(0.f, 0.f, 0.f, 0.f);
#pragma unroll
    for (int v = 0; v < Vv; v++) {
        const float4 pv = *(const float4*)(P + ((size_t)((b * Vv + v) * Nn + n)) * Cc + ch);
        acc.x += sv[v] * pv.x; acc.y += sv[v] * pv.y;
        acc.z += sv[v] * pv.z; acc.w += sv[v] * pv.w;
    }
    if (last) {
        *(float4*)(OutC + (size_t)bn * Cc + ch) = acc;
        if (threadIdx.x == 0) {
            float ent = 0.f;
#pragma unroll
            for (int v = 0; v < Vv; v++) ent -= sv[v] * logf(sv[v] + 1e-8f);
            Rout[bn] = 1.0f - ent / logf((float)Vv);
        }
    } else {
        union { uint16_t u[4]; uint2 p; } hh, ll;
        split1(acc.x, hh.u[0], ll.u[0]);
        split1(acc.y, hh.u[1], ll.u[1]);
        split1(acc.z, hh.u[2], ll.u[2]);
        split1(acc.w, hh.u[3], ll.u[3]);
        size_t o = (size_t)bn * Cc + ch;
        *(uint2*)(g_ch + o) = hh.p;
        *(uint2*)(g_cl + o) = ll.p;
    }
}

// ---------------------------------------------------------------------------
// Launch
// ---------------------------------------------------------------------------
extern "C" void kernel_launch(void* const* d_in, const int* in_sizes, int n_in,
                              void* d_out, int out_size) {
    const float* x       = (const float*)d_in[0];
    const float* w_views = (const float*)d_in[1];
    const float* w1      = (const float*)d_in[2];
    const float* b1      = (const float*)d_in[3];
    const float* w2      = (const float*)d_in[4];
    const float* b2      = (const float*)d_in[5];
    float* out = (float*)d_out;   // c [B,N,C] then r [B,N]

    float *P, *XW1, *CW1, *S;
    __nv_bfloat16 *xh, *xl, *ch, *cl, *Wh, *Wl;
    cudaGetSymbolAddress((void**)&P,   g_P);
    cudaGetSymbolAddress((void**)&XW1, g_XW1);
    cudaGetSymbolAddress((void**)&CW1, g_CW1);
    cudaGetSymbolAddress((void**)&S,   g_S);
    cudaGetSymbolAddress((void**)&xh,  g_xh);
    cudaGetSymbolAddress((void**)&xl,  g_xl);
    cudaGetSymbolAddress((void**)&ch,  g_ch);
    cudaGetSymbolAddress((void**)&cl,  g_cl);
    cudaGetSymbolAddress((void**)&Wh,  g_Wh);
    cudaGetSymbolAddress((void**)&Wl,  g_Wl);

    cudaFuncSetAttribute(mma_gemm<0>, cudaFuncAttributeMaxDynamicSharedMemorySize, SMEM_TOTAL);
    cudaFuncSetAttribute(mma_gemm<1>, cudaFuncAttributeMaxDynamicSharedMemorySize, SMEM_TOTAL);

    // conversions
    {
        size_t tot = (size_t)BVN * Cc / 4;
        split_x_kernel<<<(unsigned)((tot + 255) / 256), 256>>>(x);
        size_t tw = (size_t)7 * WMAT;
        split_w_kernel<<<(unsigned)((tw + 255) / 256), 256>>>(w_views, w1);
        int tm = BN_ROWS * (Cc / 4);
        mean_kernel<<<(tm + 255) / 256, 256>>>(x);
    }
    // proj_x = x @ w_views (per view)
    {
        dim3 grid(Cc / 128, BN_ROWS / 128, Vv);   // (6, 49, 5)
        mma_gemm<1><<<grid, 256, SMEM_TOTAL>>>(xh, xl, Wh, Wl, P);
    }
    // XW1 = x @ w1[:C]
    {
        dim3 grid(Hh / 128, BVN / 128, 1);        // (6, 245)
        mma_gemm<0><<<grid, 256, SMEM_TOTAL>>>(xh, xl, Wh + (size_t)5 * WMAT, Wl + (size_t)5 * WMAT, XW1);
    }
    // iterations
    for (int it = 0; it < NUM_ITERS; it++) {
        dim3 gridc(Hh / 128, BN_ROWS / 128, 1);   // (6, 49)
        mma_gemm<0><<<gridc, 256, SMEM_TOTAL>>>(ch, cl, Wh + (size_t)6 * WMAT, Wl + (size_t)6 * WMAT, CW1);

        int blocks = (BVN * 32 + 255) / 256;
        score_kernel<<<blocks, 256>>>(XW1, CW1, b1, w2, b2, S);

        int last = (it == NUM_ITERS - 1) ? 1 : 0;
        float* rdst = out + (size_t)BN_ROWS * Cc;
        update_kernel<<<BN_ROWS, 192>>>(S, P, out, rdst, last);
    }
    (void)in_sizes; (void)n_in; (void)out_size;
}

// round 7
// speedup vs baseline: 1.6007x; 1.3958x over previous
#include <cuda_runtime.h>
#include <cuda_fp16.h>
#include <cstdint>

#define Bb 32
#define Vv 5
#define Nn 196
#define Cc 768
#define Hh 768
#define BN_ROWS 6272            // Bb*Nn
#define BVN 31360               // Bb*Vv*Nn
#define NUM_ITERS 3
#define WMAT (Cc*Cc)            // 589824

// ---------------------------------------------------------------------------
// Scratch (device globals; no runtime allocation allowed)
// ---------------------------------------------------------------------------
__device__ float g_P[(size_t)BVN * Cc];        // proj_x   fp32
__device__ float g_XW1[(size_t)BVN * Hh];      // x @ w1[:C]
__device__ float g_CW1[(size_t)BN_ROWS * Hh];  // c @ w1[C:]
__device__ float g_S[BVN];                     // scores
__device__ __half g_xh[(size_t)BVN * Cc];      // x hi (fp16)
__device__ __half g_xl[(size_t)BVN * Cc];      // x lo (fp16)
__device__ __half g_ch[(size_t)BN_ROWS * Cc];  // c hi
__device__ __half g_cl[(size_t)BN_ROWS * Cc];  // c lo
// 7 transposed [N,K] weight matrices (single fp16): views 0..4, w1a=5, w1b=6
__device__ __half g_W[(size_t)7 * WMAT];

// ---------------------------------------------------------------------------
// Helpers
// ---------------------------------------------------------------------------
__device__ __forceinline__ uint32_t su32(const void* p) {
    uint32_t a;
    asm("{ .reg .u64 t; cvta.to.shared.u64 t, %1; cvt.u32.u64 %0, t; }" : "=r"(a) : "l"(p));
    return a;
}
__device__ __forceinline__ void cpa16(uint32_t d, const void* s) {
    asm volatile("cp.async.cg.shared.global [%0], [%1], 16;" :: "r"(d), "l"(s) : "memory");
}
__device__ __forceinline__ void cp_commit() {
    asm volatile("cp.async.commit_group;" ::: "memory");
}
__device__ __forceinline__ void ldsm4(uint32_t& r0, uint32_t& r1, uint32_t& r2, uint32_t& r3,
                                      uint32_t addr) {
    asm volatile("ldmatrix.sync.aligned.m8n8.x4.shared.b16 {%0,%1,%2,%3}, [%4];"
                 : "=r"(r0), "=r"(r1), "=r"(r2), "=r"(r3) : "r"(addr));
}
__device__ __forceinline__ void mma16816(float* d, const uint32_t* a, const uint32_t* b) {
    asm volatile(
        "mma.sync.aligned.m16n8k16.row.col.f32.f16.f16.f32 "
        "{%0,%1,%2,%3}, {%4,%5,%6,%7}, {%8,%9}, {%0,%1,%2,%3};"
        : "+f"(d[0]), "+f"(d[1]), "+f"(d[2]), "+f"(d[3])
        : "r"(a[0]), "r"(a[1]), "r"(a[2]), "r"(a[3]), "r"(b[0]), "r"(b[1]));
}

// fp16 hi/lo split: a = hi + lo exactly to ~2^-22 relative
__device__ __forceinline__ void split1(float a, uint16_t& h, uint16_t& l) {
    __half hh = __float2half_rn(a);
    __half ll = __float2half_rn(a - __half2float(hh));
    h = *(uint16_t*)&hh;
    l = *(uint16_t*)&ll;
}

// ---------------------------------------------------------------------------
// Split x into fp16 hi/lo
// ---------------------------------------------------------------------------
__global__ void split_x_kernel(const float* __restrict__ x) {
    size_t i = (size_t)blockIdx.x * blockDim.x + threadIdx.x;
    const size_t TOT = (size_t)BVN * Cc / 4;
    if (i >= TOT) return;
    float4 v = *(const float4*)(x + i * 4);
    union { uint16_t u[4]; uint2 p; } hh, ll;
    split1(v.x, hh.u[0], ll.u[0]);
    split1(v.y, hh.u[1], ll.u[1]);
    split1(v.z, hh.u[2], ll.u[2]);
    split1(v.w, hh.u[3], ll.u[3]);
    *(uint2*)(g_xh + i * 4) = hh.p;
    *(uint2*)(g_xl + i * 4) = ll.p;
}

// ---------------------------------------------------------------------------
// Transpose weights into g_W ([N,K] K-major, 7 matrices, single fp16)
// ---------------------------------------------------------------------------
__global__ void split_w_kernel(const float* __restrict__ w_views, const float* __restrict__ w1) {
    size_t j = (size_t)blockIdx.x * blockDim.x + threadIdx.x;
    const size_t TOT = (size_t)7 * WMAT;
    if (j >= TOT) return;
    int m = (int)(j / WMAT);
    int r = (int)(j % WMAT);
    int n = r / Cc, k = r % Cc;
    float s;
    if (m < 5)       s = w_views[(size_t)m * WMAT + (size_t)k * Cc + n];
    else if (m == 5) s = w1[(size_t)k * Hh + n];
    else             s = w1[(size_t)(Cc + k) * Hh + n];
    g_W[j] = __float2half_rn(s);
}

// ---------------------------------------------------------------------------
// Mean over views -> c0 as fp16 hi/lo
// ---------------------------------------------------------------------------
__global__ void mean_kernel(const float* __restrict__ x) {
    int i = blockIdx.x * blockDim.x + threadIdx.x;
    const int TOT = BN_ROWS * (Cc / 4);
    if (i >= TOT) return;
    int bn = i / (Cc / 4);
    int cq = (i % (Cc / 4)) * 4;
    int b = bn / Nn, n = bn % Nn;
    float4 acc = make_float4(0.f, 0.f, 0.f, 0.f);
#pragma unroll
    for (int v = 0; v < Vv; v++) {
        const float4 xv = *(const float4*)(x + ((size_t)((b * Vv + v) * Nn + n)) * Cc + cq);
        acc.x += xv.x; acc.y += xv.y; acc.z += xv.z; acc.w += xv.w;
    }
    const float s = 1.0f / Vv;
    acc.x *= s; acc.y *= s; acc.z *= s; acc.w *= s;
    union { uint16_t u[4]; uint2 p; } hh, ll;
    split1(acc.x, hh.u[0], ll.u[0]);
    split1(acc.y, hh.u[1], ll.u[1]);
    split1(acc.z, hh.u[2], ll.u[2]);
    split1(acc.w, hh.u[3], ll.u[3]);
    size_t o = (size_t)bn * Cc + cq;
    *(uint2*)(g_ch + o) = hh.p;
    *(uint2*)(g_cl + o) = ll.p;
}

// ---------------------------------------------------------------------------
// mma.sync fp16x2 GEMM: D = (Ah + Al) @ B, B single fp16.
// CTA 128x128, 8 warps (2M x 4N), warp tile 64x32, K=768 in 12 chunks of 64.
// Stage 48KB: Ah/Al/B 16KB each; 2 stages (96KB).
// MODE 0: flat rows. MODE 1: per-view gather/scatter (v = blockIdx.z).
// ---------------------------------------------------------------------------
#define STAGE_BYTES 49152          // 3 tiles x 16KB (Ah, Al, B)
#define SMEM_TOTAL  (2 * STAGE_BYTES)
#define OFF_AL 16384
#define OFF_B  32768
#define NCHUNK 12

template <int MODE>
__global__ __launch_bounds__(256, 1)
void mma_gemm(const __half* __restrict__ Ah, const __half* __restrict__ Al,
              const __half* __restrict__ Bw, float* __restrict__ Cout) {
    extern __shared__ char smem[];
    const uint32_t sb = su32(smem);
    const int tid = threadIdx.x;
    const int lane = tid & 31;
    const int wid = tid >> 5;
    const int warpM = wid & 1;
    const int warpN = wid >> 1;
    const int MBase = blockIdx.y * 128;
    const int NBase = blockIdx.x * 128;
    const int v = blockIdx.z;

    if (MODE == 1) { Bw += (size_t)v * WMAT; }

    // ---- load geometry: each thread owns one tile-row half (64B) ----
    const int lr = tid >> 1;                 // tile row 0..127
    const int lc = (tid & 1) * 64;           // byte offset within 128B row
    int gaRow;
    if (MODE == 1) {
        int bn = MBase + lr;
        int b = bn / Nn, n = bn - b * Nn;
        gaRow = (b * Vv + v) * Nn + n;
    } else {
        gaRow = MBase + lr;
    }
    const char* aRowPtr = (const char*)(Ah + (size_t)gaRow * Cc) + lc;
    const char* bRowPtr = (const char*)(Bw + (size_t)(NBase + lr) * Cc) + lc;
    const ptrdiff_t dAl = (const char*)Al - (const char*)Ah;
    uint32_t so[4];
#pragma unroll
    for (int j = 0; j < 4; j++)
        so[j] = (uint32_t)(lr * 128 + ((lc + j * 16) ^ ((lr & 7) << 4)));

    auto issue = [&](int chunk, int stg) {
        uint32_t base = sb + stg * STAGE_BYTES;
        const char* pa = aRowPtr + chunk * 128;
        const char* pb = bRowPtr + chunk * 128;
#pragma unroll
        for (int j = 0; j < 4; j++) {
            cpa16(base + so[j], pa + j * 16);
            cpa16(base + OFF_AL + so[j], pa + dAl + j * 16);
            cpa16(base + OFF_B + so[j], pb + j * 16);
        }
        cp_commit();
    };

    float acc[4][4][4];
#pragma unroll
    for (int mt = 0; mt < 4; mt++)
#pragma unroll
        for (int nt = 0; nt < 4; nt++)
#pragma unroll
            for (int e = 0; e < 4; e++) acc[mt][nt][e] = 0.f;

    const uint32_t swz = (uint32_t)((lane & 7) << 4);
    const uint32_t aRow0 = (uint32_t)(warpM * 64 + (lane & 15));
    const uint32_t nRow0 = (uint32_t)(warpN * 32 + (lane & 15));
    const uint32_t halfSel = (uint32_t)((lane >> 4) << 4);   // 0 or 16 bytes

    issue(0, 0);
#pragma unroll 1
    for (int i = 0; i < NCHUNK; i++) {
        int stg = i & 1;
        if (i + 1 < NCHUNK) {
            issue(i + 1, stg ^ 1);
            asm volatile("cp.async.wait_group 1;" ::: "memory");
        } else {
            asm volatile("cp.async.wait_group 0;" ::: "memory");
        }
        __syncthreads();

        uint32_t base = sb + stg * STAGE_BYTES;
#pragma unroll
        for (int k16 = 0; k16 < 4; k16++) {
            const uint32_t bc = (uint32_t)(k16 * 32) + halfSel;
            uint32_t ah[4][4], al[4][4], bh[4][2];
#pragma unroll
            for (int mt = 0; mt < 4; mt++) {
                uint32_t ad = base + (aRow0 + mt * 16) * 128 + (bc ^ swz);
                ldsm4(ah[mt][0], ah[mt][1], ah[mt][2], ah[mt][3], ad);
                ldsm4(al[mt][0], al[mt][1], al[mt][2], al[mt][3], ad + OFF_AL);
            }
#pragma unroll
            for (int g = 0; g < 2; g++) {
                uint32_t ad = base + OFF_B + (nRow0 + g * 16) * 128 + (bc ^ swz);
                uint32_t r0, r1, r2, r3;
                ldsm4(r0, r1, r2, r3, ad);
                bh[g * 2 + 0][0] = r0; bh[g * 2 + 0][1] = r2;
                bh[g * 2 + 1][0] = r1; bh[g * 2 + 1][1] = r3;
            }
#pragma unroll
            for (int mt = 0; mt < 4; mt++)
#pragma unroll
                for (int nt = 0; nt < 4; nt++) {
                    mma16816(acc[mt][nt], ah[mt], bh[nt]);
                    mma16816(acc[mt][nt], al[mt], bh[nt]);
                }
        }
        __syncthreads();
    }

    // ---- epilogue ----
    int grow[8];
#pragma unroll
    for (int mt = 0; mt < 4; mt++) {
#pragma unroll
        for (int h = 0; h < 2; h++) {
            int m = MBase + warpM * 64 + mt * 16 + (lane >> 2) + h * 8;
            if (MODE == 1) {
                int b = m / Nn, n = m - b * Nn;
                grow[mt * 2 + h] = (b * Vv + v) * Nn + n;
            } else {
                grow[mt * 2 + h] = m;
            }
        }
    }
    const int ncol0 = NBase + warpN * 32 + (lane & 3) * 2;
#pragma unroll
    for (int mt = 0; mt < 4; mt++)
#pragma unroll
        for (int nt = 0; nt < 4; nt++) {
            float* p0 = Cout + (size_t)grow[mt * 2 + 0] * Cc + ncol0 + nt * 8;
            float* p1 = Cout + (size_t)grow[mt * 2 + 1] * Cc + ncol0 + nt * 8;
            p0[0] = acc[mt][nt][0]; p0[1] = acc[mt][nt][1];
            p1[0] = acc[mt][nt][2]; p1[1] = acc[mt][nt][3];
        }
}

// ---------------------------------------------------------------------------
// Score: one warp per (b,v,n) row. s = dot(tanh(XW1+CW1+b1), w2) + b2
// ---------------------------------------------------------------------------
__global__ void score_kernel(const float* __restrict__ XW1, const float* __restrict__ CW1,
                             const float* __restrict__ b1, const float* __restrict__ w2,
                             const float* __restrict__ b2, float* __restrict__ S) {
    int gwarp = (blockIdx.x * blockDim.x + threadIdx.x) >> 5;
    int lane = threadIdx.x & 31;
    if (gwarp >= BVN) return;
    int b = gwarp / (Vv * Nn);
    int rem = gwarp % (Vv * Nn);
    int n = rem % Nn;
    const float* xr = XW1 + (size_t)gwarp * Hh;
    const float* cr = CW1 + (size_t)(b * Nn + n) * Hh;
    float sum = 0.f;
#pragma unroll
    for (int h = lane * 4; h < Hh; h += 128) {
        float4 xv = *(const float4*)(xr + h);
        float4 cv = *(const float4*)(cr + h);
        float4 bb = *(const float4*)(b1 + h);
        float4 wv = *(const float4*)(w2 + h);
        sum += tanhf(xv.x + cv.x + bb.x) * wv.x;
        sum += tanhf(xv.y + cv.y + bb.y) * wv.y;
        sum += tanhf(xv.z + cv.z + bb.z) * wv.z;
        sum += tanhf(xv.w + cv.w + bb.w) * wv.w;
    }
#pragma unroll
    for (int off = 16; off; off >>= 1) sum += __shfl_xor_sync(0xFFFFFFFFu, sum, off);
    if (lane == 0) S[gwarp] = sum + b2[0];
}

// ---------------------------------------------------------------------------
// Softmax over views + weighted-sum update.
// Non-last iters: write c as fp16 hi/lo. Last iter: write fp32 c + r.
// ---------------------------------------------------------------------------
__global__ void update_kernel(const float* __restrict__ S, const float* __restrict__ P,
                              float* __restrict__ OutC, float* __restrict__ Rout, int last) {
    int bn = blockIdx.x;
    int b = bn / Nn, n = bn % Nn;
    float sv[Vv];
    float mx = -1e30f;
#pragma unroll
    for (int v = 0; v < Vv; v++) {
        sv[v] = S[(size_t)(b * Vv + v) * Nn + n];
        mx = fmaxf(mx, sv[v]);
    }
    float den = 0.f;
#pragma unroll
    for (int v = 0; v < Vv; v++) { sv[v] = expf(sv[v] - mx); den += sv[v]; }
    float inv = 1.0f / den;
#pragma unroll
    for (int v = 0; v < Vv; v++) sv[v] *= inv;

    int ch = threadIdx.x * 4;
    float4 acc = make_float4(0.f, 0.f, 0.f, 0.f);
#pragma unroll
    for (int v = 0; v < Vv; v++) {
        const float4 pv = *(const float4*)(P + ((size_t)((b * Vv + v) * Nn + n)) * Cc + ch);
        acc.x += sv[v] * pv.x; acc.y += sv[v] * pv.y;
        acc.z += sv[v] * pv.z; acc.w += sv[v] * pv.w;
    }
    if (last) {
        *(float4*)(OutC + (size_t)bn * Cc + ch) = acc;
        if (threadIdx.x == 0) {
            float ent = 0.f;
#pragma unroll
            for (int v = 0; v < Vv; v++) ent -= sv[v] * logf(sv[v] + 1e-8f);
            Rout[bn] = 1.0f - ent / logf((float)Vv);
        }
    } else {
        union { uint16_t u[4]; uint2 p; } hh, ll;
        split1(acc.x, hh.u[0], ll.u[0]);
        split1(acc.y, hh.u[1], ll.u[1]);
        split1(acc.z, hh.u[2], ll.u[2]);
        split1(acc.w, hh.u[3], ll.u[3]);
        size_t o = (size_t)bn * Cc + ch;
        *(uint2*)(g_ch + o) = hh.p;
        *(uint2*)(g_cl + o) = ll.p;
    }
}

// ---------------------------------------------------------------------------
// Launch
// ---------------------------------------------------------------------------
extern "C" void kernel_launch(void* const* d_in, const int* in_sizes, int n_in,
                              void* d_out, int out_size) {
    const float* x       = (const float*)d_in[0];
    const float* w_views = (const float*)d_in[1];
    const float* w1      = (const float*)d_in[2];
    const float* b1      = (const float*)d_in[3];
    const float* w2      = (const float*)d_in[4];
    const float* b2      = (const float*)d_in[5];
    float* out = (float*)d_out;   // c [B,N,C] then r [B,N]

    float *P, *XW1, *CW1, *S;
    __half *xh, *xl, *ch, *cl, *W;
    cudaGetSymbolAddress((void**)&P,   g_P);
    cudaGetSymbolAddress((void**)&XW1, g_XW1);
    cudaGetSymbolAddress((void**)&CW1, g_CW1);
    cudaGetSymbolAddress((void**)&S,   g_S);
    cudaGetSymbolAddress((void**)&xh,  g_xh);
    cudaGetSymbolAddress((void**)&xl,  g_xl);
    cudaGetSymbolAddress((void**)&ch,  g_ch);
    cudaGetSymbolAddress((void**)&cl,  g_cl);
    cudaGetSymbolAddress((void**)&W,   g_W);

    cudaFuncSetAttribute(mma_gemm<0>, cudaFuncAttributeMaxDynamicSharedMemorySize, SMEM_TOTAL);
    cudaFuncSetAttribute(mma_gemm<1>, cudaFuncAttributeMaxDynamicSharedMemorySize, SMEM_TOTAL);

    // conversions
    {
        size_t tot = (size_t)BVN * Cc / 4;
        split_x_kernel<<<(unsigned)((tot + 255) / 256), 256>>>(x);
        size_t tw = (size_t)7 * WMAT;
        split_w_kernel<<<(unsigned)((tw + 255) / 256), 256>>>(w_views, w1);
        int tm = BN_ROWS * (Cc / 4);
        mean_kernel<<<(tm + 255) / 256, 256>>>(x);
    }
    // proj_x = x @ w_views (per view)
    {
        dim3 grid(Cc / 128, BN_ROWS / 128, Vv);   // (6, 49, 5)
        mma_gemm<1><<<grid, 256, SMEM_TOTAL>>>(xh, xl, W, P);
    }
    // XW1 = x @ w1[:C]
    {
        dim3 grid(Hh / 128, BVN / 128, 1);        // (6, 245)
        mma_gemm<0><<<grid, 256, SMEM_TOTAL>>>(xh, xl, W + (size_t)5 * WMAT, XW1);
    }
    // iterations
    for (int it = 0; it < NUM_ITERS; it++) {
        dim3 gridc(Hh / 128, BN_ROWS / 128, 1);   // (6, 49)
        mma_gemm<0><<<gridc, 256, SMEM_TOTAL>>>(ch, cl, W + (size_t)6 * WMAT, CW1);

        int blocks = (BVN * 32 + 255) / 256;
        score_kernel<<<blocks, 256>>>(XW1, CW1, b1, w2, b2, S);

        int last = (it == NUM_ITERS - 1) ? 1 : 0;
        float* rdst = out + (size_t)BN_ROWS * Cc;
        update_kernel<<<BN_ROWS, 192>>>(S, P, out, rdst, last);
    }
    (void)in_sizes; (void)n_in; (void)out_size;
}

// round 8
// speedup vs baseline: 2.3492x; 1.4677x over previous
#include <cuda_runtime.h>
#include <cuda_fp16.h>
#include <cstdint>

#define Bb 32
#define Vv 5
#define Nn 196
#define Cc 768
#define Hh 768
#define BN_ROWS 6272            // Bb*Nn
#define BVN 31360               // Bb*Vv*Nn
#define NUM_ITERS 3
#define WMAT (Cc*Cc)            // 589824

// ---------------------------------------------------------------------------
// Scratch (device globals; no runtime allocation allowed)
// ---------------------------------------------------------------------------
__device__ float g_P[(size_t)BVN * Cc];        // proj_x   fp32
__device__ float g_XW1[(size_t)BVN * Hh];      // x @ w1[:C]
__device__ float g_CW1[(size_t)BN_ROWS * Hh];  // c @ w1[C:]
__device__ float g_S[BVN];                     // scores
__device__ __half g_xh[(size_t)BVN * Cc];      // x (fp16)
__device__ __half g_ch[(size_t)BN_ROWS * Cc];  // c (fp16)
// 7 transposed [N,K] weight matrices (fp16): views 0..4, w1a=5, w1b=6
__device__ __half g_W[(size_t)7 * WMAT];

// ---------------------------------------------------------------------------
// Helpers
// ---------------------------------------------------------------------------
__device__ __forceinline__ uint32_t su32(const void* p) {
    uint32_t a;
    asm("{ .reg .u64 t; cvta.to.shared.u64 t, %1; cvt.u32.u64 %0, t; }" : "=r"(a) : "l"(p));
    return a;
}
__device__ __forceinline__ void cpa16(uint32_t d, const void* s) {
    asm volatile("cp.async.cg.shared.global [%0], [%1], 16;" :: "r"(d), "l"(s) : "memory");
}
__device__ __forceinline__ void cp_commit() {
    asm volatile("cp.async.commit_group;" ::: "memory");
}
__device__ __forceinline__ void ldsm4(uint32_t& r0, uint32_t& r1, uint32_t& r2, uint32_t& r3,
                                      uint32_t addr) {
    asm volatile("ldmatrix.sync.aligned.m8n8.x4.shared.b16 {%0,%1,%2,%3}, [%4];"
                 : "=r"(r0), "=r"(r1), "=r"(r2), "=r"(r3) : "r"(addr));
}
__device__ __forceinline__ void mma16816(float* d, const uint32_t* a, const uint32_t* b) {
    asm volatile(
        "mma.sync.aligned.m16n8k16.row.col.f32.f16.f16.f32 "
        "{%0,%1,%2,%3}, {%4,%5,%6,%7}, {%8,%9}, {%0,%1,%2,%3};"
        : "+f"(d[0]), "+f"(d[1]), "+f"(d[2]), "+f"(d[3])
        : "r"(a[0]), "r"(a[1]), "r"(a[2]), "r"(a[3]), "r"(b[0]), "r"(b[1]));
}

// ---------------------------------------------------------------------------
// Convert x to fp16
// ---------------------------------------------------------------------------
__global__ void split_x_kernel(const float* __restrict__ x) {
    size_t i = (size_t)blockIdx.x * blockDim.x + threadIdx.x;
    const size_t TOT = (size_t)BVN * Cc / 4;
    if (i >= TOT) return;
    float4 v = *(const float4*)(x + i * 4);
    __half2 a = __floats2half2_rn(v.x, v.y);
    __half2 b = __floats2half2_rn(v.z, v.w);
    uint2 p;
    p.x = *(uint32_t*)&a;
    p.y = *(uint32_t*)&b;
    *(uint2*)(g_xh + i * 4) = p;
}

// ---------------------------------------------------------------------------
// Transpose weights into g_W ([N,K] K-major, 7 matrices, fp16)
// ---------------------------------------------------------------------------
__global__ void split_w_kernel(const float* __restrict__ w_views, const float* __restrict__ w1) {
    size_t j = (size_t)blockIdx.x * blockDim.x + threadIdx.x;
    const size_t TOT = (size_t)7 * WMAT;
    if (j >= TOT) return;
    int m = (int)(j / WMAT);
    int r = (int)(j % WMAT);
    int n = r / Cc, k = r % Cc;
    float s;
    if (m < 5)       s = w_views[(size_t)m * WMAT + (size_t)k * Cc + n];
    else if (m == 5) s = w1[(size_t)k * Hh + n];
    else             s = w1[(size_t)(Cc + k) * Hh + n];
    g_W[j] = __float2half_rn(s);
}

// ---------------------------------------------------------------------------
// Mean over views -> c0 (fp16)
// ---------------------------------------------------------------------------
__global__ void mean_kernel(const float* __restrict__ x) {
    int i = blockIdx.x * blockDim.x + threadIdx.x;
    const int TOT = BN_ROWS * (Cc / 4);
    if (i >= TOT) return;
    int bn = i / (Cc / 4);
    int cq = (i % (Cc / 4)) * 4;
    int b = bn / Nn, n = bn % Nn;
    float4 acc = make_float4(0.f, 0.f, 0.f, 0.f);
#pragma unroll
    for (int v = 0; v < Vv; v++) {
        const float4 xv = *(const float4*)(x + ((size_t)((b * Vv + v) * Nn + n)) * Cc + cq);
        acc.x += xv.x; acc.y += xv.y; acc.z += xv.z; acc.w += xv.w;
    }
    const float s = 1.0f / Vv;
    __half2 a = __floats2half2_rn(acc.x * s, acc.y * s);
    __half2 bq = __floats2half2_rn(acc.z * s, acc.w * s);
    uint2 p;
    p.x = *(uint32_t*)&a;
    p.y = *(uint32_t*)&bq;
    *(uint2*)(g_ch + (size_t)bn * Cc + cq) = p;
}

// ---------------------------------------------------------------------------
// mma.sync fp16 GEMM: D = A @ B^T, both fp16.
// CTA 128x128, 8 warps (2M x 4N), warp tile 64x32, K=768 in 12 chunks of 64.
// Stage 32KB: A/B 16KB each; 2 stages (64KB) -> 2 CTAs/SM.
// MODE 0: flat rows. MODE 1: per-view gather/scatter (v = blockIdx.z).
// ---------------------------------------------------------------------------
#define STAGE_BYTES 32768          // 2 tiles x 16KB (A, B)
#define SMEM_TOTAL  (2 * STAGE_BYTES)
#define OFF_B  16384
#define NCHUNK 12

template <int MODE>
__global__ __launch_bounds__(256, 2)
void mma_gemm(const __half* __restrict__ Aw, const __half* __restrict__ Bw,
              float* __restrict__ Cout) {
    extern __shared__ char smem[];
    const uint32_t sb = su32(smem);
    const int tid = threadIdx.x;
    const int lane = tid & 31;
    const int wid = tid >> 5;
    const int warpM = wid & 1;
    const int warpN = wid >> 1;
    const int MBase = blockIdx.y * 128;
    const int NBase = blockIdx.x * 128;
    const int v = blockIdx.z;

    if (MODE == 1) { Bw += (size_t)v * WMAT; }

    // ---- load geometry: each thread owns one tile-row half (64B) ----
    const int lr = tid >> 1;                 // tile row 0..127
    const int lc = (tid & 1) * 64;           // byte offset within 128B row
    int gaRow;
    if (MODE == 1) {
        int bn = MBase + lr;
        int b = bn / Nn, n = bn - b * Nn;
        gaRow = (b * Vv + v) * Nn + n;
    } else {
        gaRow = MBase + lr;
    }
    const char* aRowPtr = (const char*)(Aw + (size_t)gaRow * Cc) + lc;
    const char* bRowPtr = (const char*)(Bw + (size_t)(NBase + lr) * Cc) + lc;
    uint32_t so[4];
#pragma unroll
    for (int j = 0; j < 4; j++)
        so[j] = (uint32_t)(lr * 128 + ((lc + j * 16) ^ ((lr & 7) << 4)));

    auto issue = [&](int chunk, int stg) {
        uint32_t base = sb + stg * STAGE_BYTES;
        const char* pa = aRowPtr + chunk * 128;
        const char* pb = bRowPtr + chunk * 128;
#pragma unroll
        for (int j = 0; j < 4; j++) {
            cpa16(base + so[j], pa + j * 16);
            cpa16(base + OFF_B + so[j], pb + j * 16);
        }
        cp_commit();
    };

    float acc[4][4][4];
#pragma unroll
    for (int mt = 0; mt < 4; mt++)
#pragma unroll
        for (int nt = 0; nt < 4; nt++)
#pragma unroll
            for (int e = 0; e < 4; e++) acc[mt][nt][e] = 0.f;

    const uint32_t swz = (uint32_t)((lane & 7) << 4);
    const uint32_t aRow0 = (uint32_t)(warpM * 64 + (lane & 15));
    const uint32_t nRow0 = (uint32_t)(warpN * 32 + (lane & 15));
    const uint32_t halfSel = (uint32_t)((lane >> 4) << 4);   // 0 or 16 bytes

    issue(0, 0);
#pragma unroll 1
    for (int i = 0; i < NCHUNK; i++) {
        int stg = i & 1;
        if (i + 1 < NCHUNK) {
            issue(i + 1, stg ^ 1);
            asm volatile("cp.async.wait_group 1;" ::: "memory");
        } else {
            asm volatile("cp.async.wait_group 0;" ::: "memory");
        }
        __syncthreads();

        uint32_t base = sb + stg * STAGE_BYTES;
#pragma unroll
        for (int k16 = 0; k16 < 4; k16++) {
            const uint32_t bc = (uint32_t)(k16 * 32) + halfSel;
            uint32_t ah[4][4], bh[4][2];
#pragma unroll
            for (int mt = 0; mt < 4; mt++) {
                uint32_t ad = base + (aRow0 + mt * 16) * 128 + (bc ^ swz);
                ldsm4(ah[mt][0], ah[mt][1], ah[mt][2], ah[mt][3], ad);
            }
#pragma unroll
            for (int g = 0; g < 2; g++) {
                uint32_t ad = base + OFF_B + (nRow0 + g * 16) * 128 + (bc ^ swz);
                uint32_t r0, r1, r2, r3;
                ldsm4(r0, r1, r2, r3, ad);
                bh[g * 2 + 0][0] = r0; bh[g * 2 + 0][1] = r2;
                bh[g * 2 + 1][0] = r1; bh[g * 2 + 1][1] = r3;
            }
#pragma unroll
            for (int mt = 0; mt < 4; mt++)
#pragma unroll
                for (int nt = 0; nt < 4; nt++)
                    mma16816(acc[mt][nt], ah[mt], bh[nt]);
        }
        __syncthreads();
    }

    // ---- epilogue ----
    int grow[8];
#pragma unroll
    for (int mt = 0; mt < 4; mt++) {
#pragma unroll
        for (int h = 0; h < 2; h++) {
            int m = MBase + warpM * 64 + mt * 16 + (lane >> 2) + h * 8;
            if (MODE == 1) {
                int b = m / Nn, n = m - b * Nn;
                grow[mt * 2 + h] = (b * Vv + v) * Nn + n;
            } else {
                grow[mt * 2 + h] = m;
            }
        }
    }
    const int ncol0 = NBase + warpN * 32 + (lane & 3) * 2;
#pragma unroll
    for (int mt = 0; mt < 4; mt++)
#pragma unroll
        for (int nt = 0; nt < 4; nt++) {
            float* p0 = Cout + (size_t)grow[mt * 2 + 0] * Cc + ncol0 + nt * 8;
            float* p1 = Cout + (size_t)grow[mt * 2 + 1] * Cc + ncol0 + nt * 8;
            p0[0] = acc[mt][nt][0]; p0[1] = acc[mt][nt][1];
            p1[0] = acc[mt][nt][2]; p1[1] = acc[mt][nt][3];
        }
}

// ---------------------------------------------------------------------------
// Score: one warp per (b,v,n) row. s = dot(tanh(XW1+CW1+b1), w2) + b2
// ---------------------------------------------------------------------------
__global__ void score_kernel(const float* __restrict__ XW1, const float* __restrict__ CW1,
                             const float* __restrict__ b1, const float* __restrict__ w2,
                             const float* __restrict__ b2, float* __restrict__ S) {
    int gwarp = (blockIdx.x * blockDim.x + threadIdx.x) >> 5;
    int lane = threadIdx.x & 31;
    if (gwarp >= BVN) return;
    int b = gwarp / (Vv * Nn);
    int rem = gwarp % (Vv * Nn);
    int n = rem % Nn;
    const float* xr = XW1 + (size_t)gwarp * Hh;
    const float* cr = CW1 + (size_t)(b * Nn + n) * Hh;
    float sum = 0.f;
#pragma unroll
    for (int h = lane * 4; h < Hh; h += 128) {
        float4 xv = *(const float4*)(xr + h);
        float4 cv = *(const float4*)(cr + h);
        float4 bb = *(const float4*)(b1 + h);
        float4 wv = *(const float4*)(w2 + h);
        sum += tanhf(xv.x + cv.x + bb.x) * wv.x;
        sum += tanhf(xv.y + cv.y + bb.y) * wv.y;
        sum += tanhf(xv.z + cv.z + bb.z) * wv.z;
        sum += tanhf(xv.w + cv.w + bb.w) * wv.w;
    }
#pragma unroll
    for (int off = 16; off; off >>= 1) sum += __shfl_xor_sync(0xFFFFFFFFu, sum, off);
    if (lane == 0) S[gwarp] = sum + b2[0];
}

// ---------------------------------------------------------------------------
// Softmax over views + weighted-sum update.
// Non-last iters: write c as fp16. Last iter: write fp32 c + r.
// ---------------------------------------------------------------------------
__global__ void update_kernel(const float* __restrict__ S, const float* __restrict__ P,
                              float* __restrict__ OutC, float* __restrict__ Rout, int last) {
    int bn = blockIdx.x;
    int b = bn / Nn, n = bn % Nn;
    float sv[Vv];
    float mx = -1e30f;
#pragma unroll
    for (int v = 0; v < Vv; v++) {
        sv[v] = S[(size_t)(b * Vv + v) * Nn + n];
        mx = fmaxf(mx, sv[v]);
    }
    float den = 0.f;
#pragma unroll
    for (int v = 0; v < Vv; v++) { sv[v] = expf(sv[v] - mx); den += sv[v]; }
    float inv = 1.0f / den;
#pragma unroll
    for (int v = 0; v < Vv; v++) sv[v] *= inv;

    int ch = threadIdx.x * 4;
    float4 acc = make_float4(0.f, 0.f, 0.f, 0.f);
#pragma unroll
    for (int v = 0; v < Vv; v++) {
        const float4 pv = *(const float4*)(P + ((size_t)((b * Vv + v) * Nn + n)) * Cc + ch);
        acc.x += sv[v] * pv.x; acc.y += sv[v] * pv.y;
        acc.z += sv[v] * pv.z; acc.w += sv[v] * pv.w;
    }
    if (last) {
        *(float4*)(OutC + (size_t)bn * Cc + ch) = acc;
        if (threadIdx.x == 0) {
            float ent = 0.f;
#pragma unroll
            for (int v = 0; v < Vv; v++) ent -= sv[v] * logf(sv[v] + 1e-8f);
            Rout[bn] = 1.0f - ent / logf((float)Vv);
        }
    } else {
        __half2 a = __floats2half2_rn(acc.x, acc.y);
        __half2 bq = __floats2half2_rn(acc.z, acc.w);
        uint2 p;
        p.x = *(uint32_t*)&a;
        p.y = *(uint32_t*)&bq;
        *(uint2*)(g_ch + (size_t)bn * Cc + ch) = p;
    }
}

// ---------------------------------------------------------------------------
// Launch
// ---------------------------------------------------------------------------
extern "C" void kernel_launch(void* const* d_in, const int* in_sizes, int n_in,
                              void* d_out, int out_size) {
    const float* x       = (const float*)d_in[0];
    const float* w_views = (const float*)d_in[1];
    const float* w1      = (const float*)d_in[2];
    const float* b1      = (const float*)d_in[3];
    const float* w2      = (const float*)d_in[4];
    const float* b2      = (const float*)d_in[5];
    float* out = (float*)d_out;   // c [B,N,C] then r [B,N]

    float *P, *XW1, *CW1, *S;
    __half *xh, *ch, *W;
    cudaGetSymbolAddress((void**)&P,   g_P);
    cudaGetSymbolAddress((void**)&XW1, g_XW1);
    cudaGetSymbolAddress((void**)&CW1, g_CW1);
    cudaGetSymbolAddress((void**)&S,   g_S);
    cudaGetSymbolAddress((void**)&xh,  g_xh);
    cudaGetSymbolAddress((void**)&ch,  g_ch);
    cudaGetSymbolAddress((void**)&W,   g_W);

    cudaFuncSetAttribute(mma_gemm<0>, cudaFuncAttributeMaxDynamicSharedMemorySize, SMEM_TOTAL);
    cudaFuncSetAttribute(mma_gemm<1>, cudaFuncAttributeMaxDynamicSharedMemorySize, SMEM_TOTAL);

    // conversions
    {
        size_t tot = (size_t)BVN * Cc / 4;
        split_x_kernel<<<(unsigned)((tot + 255) / 256), 256>>>(x);
        size_t tw = (size_t)7 * WMAT;
        split_w_kernel<<<(unsigned)((tw + 255) / 256), 256>>>(w_views, w1);
        int tm = BN_ROWS * (Cc / 4);
        mean_kernel<<<(tm + 255) / 256, 256>>>(x);
    }
    // proj_x = x @ w_views (per view)
    {
        dim3 grid(Cc / 128, BN_ROWS / 128, Vv);   // (6, 49, 5)
        mma_gemm<1><<<grid, 256, SMEM_TOTAL>>>(xh, W, P);
    }
    // XW1 = x @ w1[:C]
    {
        dim3 grid(Hh / 128, BVN / 128, 1);        // (6, 245)
        mma_gemm<0><<<grid, 256, SMEM_TOTAL>>>(xh, W + (size_t)5 * WMAT, XW1);
    }
    // iterations
    for (int it = 0; it < NUM_ITERS; it++) {
        dim3 gridc(Hh / 128, BN_ROWS / 128, 1);   // (6, 49)
        mma_gemm<0><<<gridc, 256, SMEM_TOTAL>>>(ch, W + (size_t)6 * WMAT, CW1);

        int blocks = (BVN * 32 + 255) / 256;
        score_kernel<<<blocks, 256>>>(XW1, CW1, b1, w2, b2, S);

        int last = (it == NUM_ITERS - 1) ? 1 : 0;
        float* rdst = out + (size_t)BN_ROWS * Cc;
        update_kernel<<<BN_ROWS, 192>>>(S, P, out, rdst, last);
    }
    (void)in_sizes; (void)n_in; (void)out_size;
}

// round 9
// speedup vs baseline: 2.6434x; 1.1252x over previous
#include <cuda_runtime.h>
#include <cuda_fp16.h>
#include <cstdint>

#define Bb 32
#define Vv 5
#define Nn 196
#define Cc 768
#define Hh 768
#define BN_ROWS 6272            // Bb*Nn
#define BVN 31360               // Bb*Vv*Nn
#define NUM_ITERS 3
#define WMAT (Cc*Cc)            // 589824

// ---------------------------------------------------------------------------
// Scratch (device globals; no runtime allocation allowed) — all fp16 now
// ---------------------------------------------------------------------------
__device__ __half g_P[(size_t)BVN * Cc];        // proj_x
__device__ __half g_XW1[(size_t)BVN * Hh];      // x @ w1[:C]
__device__ __half g_CW1[(size_t)BN_ROWS * Hh];  // c @ w1[C:]
__device__ __half g_xh[(size_t)BVN * Cc];       // x (fp16)
__device__ __half g_ch[(size_t)BN_ROWS * Cc];   // c (fp16)
// 7 transposed [N,K] weight matrices (fp16): views 0..4, w1a=5, w1b=6
__device__ __half g_W[(size_t)7 * WMAT];

// ---------------------------------------------------------------------------
// Helpers
// ---------------------------------------------------------------------------
__device__ __forceinline__ uint32_t su32(const void* p) {
    uint32_t a;
    asm("{ .reg .u64 t; cvta.to.shared.u64 t, %1; cvt.u32.u64 %0, t; }" : "=r"(a) : "l"(p));
    return a;
}
__device__ __forceinline__ void cpa16(uint32_t d, const void* s) {
    asm volatile("cp.async.cg.shared.global [%0], [%1], 16;" :: "r"(d), "l"(s) : "memory");
}
__device__ __forceinline__ void cp_commit() {
    asm volatile("cp.async.commit_group;" ::: "memory");
}
__device__ __forceinline__ void ldsm4(uint32_t& r0, uint32_t& r1, uint32_t& r2, uint32_t& r3,
                                      uint32_t addr) {
    asm volatile("ldmatrix.sync.aligned.m8n8.x4.shared.b16 {%0,%1,%2,%3}, [%4];"
                 : "=r"(r0), "=r"(r1), "=r"(r2), "=r"(r3) : "r"(addr));
}
__device__ __forceinline__ void mma16816(float* d, const uint32_t* a, const uint32_t* b) {
    asm volatile(
        "mma.sync.aligned.m16n8k16.row.col.f32.f16.f16.f32 "
        "{%0,%1,%2,%3}, {%4,%5,%6,%7}, {%8,%9}, {%0,%1,%2,%3};"
        : "+f"(d[0]), "+f"(d[1]), "+f"(d[2]), "+f"(d[3])
        : "r"(a[0]), "r"(a[1]), "r"(a[2]), "r"(a[3]), "r"(b[0]), "r"(b[1]));
}

// ---------------------------------------------------------------------------
// Convert x to fp16
// ---------------------------------------------------------------------------
__global__ void split_x_kernel(const float* __restrict__ x) {
    size_t i = (size_t)blockIdx.x * blockDim.x + threadIdx.x;
    const size_t TOT = (size_t)BVN * Cc / 4;
    if (i >= TOT) return;
    float4 v = *(const float4*)(x + i * 4);
    __half2 a = __floats2half2_rn(v.x, v.y);
    __half2 b = __floats2half2_rn(v.z, v.w);
    uint2 p;
    p.x = *(uint32_t*)&a;
    p.y = *(uint32_t*)&b;
    *(uint2*)(g_xh + i * 4) = p;
}

// ---------------------------------------------------------------------------
// Transpose weights into g_W ([N,K] K-major, 7 matrices, fp16)
// ---------------------------------------------------------------------------
__global__ void split_w_kernel(const float* __restrict__ w_views, const float* __restrict__ w1) {
    size_t j = (size_t)blockIdx.x * blockDim.x + threadIdx.x;
    const size_t TOT = (size_t)7 * WMAT;
    if (j >= TOT) return;
    int m = (int)(j / WMAT);
    int r = (int)(j % WMAT);
    int n = r / Cc, k = r % Cc;
    float s;
    if (m < 5)       s = w_views[(size_t)m * WMAT + (size_t)k * Cc + n];
    else if (m == 5) s = w1[(size_t)k * Hh + n];
    else             s = w1[(size_t)(Cc + k) * Hh + n];
    g_W[j] = __float2half_rn(s);
}

// ---------------------------------------------------------------------------
// Mean over views -> c0 (fp16)
// ---------------------------------------------------------------------------
__global__ void mean_kernel(const float* __restrict__ x) {
    int i = blockIdx.x * blockDim.x + threadIdx.x;
    const int TOT = BN_ROWS * (Cc / 4);
    if (i >= TOT) return;
    int bn = i / (Cc / 4);
    int cq = (i % (Cc / 4)) * 4;
    int b = bn / Nn, n = bn % Nn;
    float4 acc = make_float4(0.f, 0.f, 0.f, 0.f);
#pragma unroll
    for (int v = 0; v < Vv; v++) {
        const float4 xv = *(const float4*)(x + ((size_t)((b * Vv + v) * Nn + n)) * Cc + cq);
        acc.x += xv.x; acc.y += xv.y; acc.z += xv.z; acc.w += xv.w;
    }
    const float s = 1.0f / Vv;
    __half2 a = __floats2half2_rn(acc.x * s, acc.y * s);
    __half2 bq = __floats2half2_rn(acc.z * s, acc.w * s);
    uint2 p;
    p.x = *(uint32_t*)&a;
    p.y = *(uint32_t*)&bq;
    *(uint2*)(g_ch + (size_t)bn * Cc + cq) = p;
}

// ---------------------------------------------------------------------------
// mma.sync fp16 GEMM: D = A @ B^T, both fp16, fp16 output.
// CTA 128x128, 8 warps (2M x 4N), warp tile 64x32, K=768 in 12 chunks of 64.
// Stage 32KB: A/B 16KB each; 2 stages (64KB) -> 2 CTAs/SM.
// MODE 0: flat rows. MODE 1: per-view gather/scatter (v = blockIdx.z).
// ---------------------------------------------------------------------------
#define STAGE_BYTES 32768          // 2 tiles x 16KB (A, B)
#define SMEM_TOTAL  (2 * STAGE_BYTES)
#define OFF_B  16384
#define NCHUNK 12

template <int MODE>
__global__ __launch_bounds__(256, 2)
void mma_gemm(const __half* __restrict__ Aw, const __half* __restrict__ Bw,
              __half* __restrict__ Cout) {
    extern __shared__ char smem[];
    const uint32_t sb = su32(smem);
    const int tid = threadIdx.x;
    const int lane = tid & 31;
    const int wid = tid >> 5;
    const int warpM = wid & 1;
    const int warpN = wid >> 1;
    const int MBase = blockIdx.y * 128;
    const int NBase = blockIdx.x * 128;
    const int v = blockIdx.z;

    if (MODE == 1) { Bw += (size_t)v * WMAT; }

    // ---- load geometry: each thread owns one tile-row half (64B) ----
    const int lr = tid >> 1;                 // tile row 0..127
    const int lc = (tid & 1) * 64;           // byte offset within 128B row
    int gaRow;
    if (MODE == 1) {
        int bn = MBase + lr;
        int b = bn / Nn, n = bn - b * Nn;
        gaRow = (b * Vv + v) * Nn + n;
    } else {
        gaRow = MBase + lr;
    }
    const char* aRowPtr = (const char*)(Aw + (size_t)gaRow * Cc) + lc;
    const char* bRowPtr = (const char*)(Bw + (size_t)(NBase + lr) * Cc) + lc;
    uint32_t so[4];
#pragma unroll
    for (int j = 0; j < 4; j++)
        so[j] = (uint32_t)(lr * 128 + ((lc + j * 16) ^ ((lr & 7) << 4)));

    auto issue = [&](int chunk, int stg) {
        uint32_t base = sb + stg * STAGE_BYTES;
        const char* pa = aRowPtr + chunk * 128;
        const char* pb = bRowPtr + chunk * 128;
#pragma unroll
        for (int j = 0; j < 4; j++) {
            cpa16(base + so[j], pa + j * 16);
            cpa16(base + OFF_B + so[j], pb + j * 16);
        }
        cp_commit();
    };

    float acc[4][4][4];
#pragma unroll
    for (int mt = 0; mt < 4; mt++)
#pragma unroll
        for (int nt = 0; nt < 4; nt++)
#pragma unroll
            for (int e = 0; e < 4; e++) acc[mt][nt][e] = 0.f;

    const uint32_t swz = (uint32_t)((lane & 7) << 4);
    const uint32_t aRow0 = (uint32_t)(warpM * 64 + (lane & 15));
    const uint32_t nRow0 = (uint32_t)(warpN * 32 + (lane & 15));
    const uint32_t halfSel = (uint32_t)((lane >> 4) << 4);   // 0 or 16 bytes

    issue(0, 0);
#pragma unroll 1
    for (int i = 0; i < NCHUNK; i++) {
        int stg = i & 1;
        if (i + 1 < NCHUNK) {
            issue(i + 1, stg ^ 1);
            asm volatile("cp.async.wait_group 1;" ::: "memory");
        } else {
            asm volatile("cp.async.wait_group 0;" ::: "memory");
        }
        __syncthreads();

        uint32_t base = sb + stg * STAGE_BYTES;
#pragma unroll
        for (int k16 = 0; k16 < 4; k16++) {
            const uint32_t bc = (uint32_t)(k16 * 32) + halfSel;
            uint32_t ah[4][4], bh[4][2];
#pragma unroll
            for (int mt = 0; mt < 4; mt++) {
                uint32_t ad = base + (aRow0 + mt * 16) * 128 + (bc ^ swz);
                ldsm4(ah[mt][0], ah[mt][1], ah[mt][2], ah[mt][3], ad);
            }
#pragma unroll
            for (int g = 0; g < 2; g++) {
                uint32_t ad = base + OFF_B + (nRow0 + g * 16) * 128 + (bc ^ swz);
                uint32_t r0, r1, r2, r3;
                ldsm4(r0, r1, r2, r3, ad);
                bh[g * 2 + 0][0] = r0; bh[g * 2 + 0][1] = r2;
                bh[g * 2 + 1][0] = r1; bh[g * 2 + 1][1] = r3;
            }
#pragma unroll
            for (int mt = 0; mt < 4; mt++)
#pragma unroll
                for (int nt = 0; nt < 4; nt++)
                    mma16816(acc[mt][nt], ah[mt], bh[nt]);
        }
        __syncthreads();
    }

    // ---- epilogue (fp16 stores) ----
    int grow[8];
#pragma unroll
    for (int mt = 0; mt < 4; mt++) {
#pragma unroll
        for (int h = 0; h < 2; h++) {
            int m = MBase + warpM * 64 + mt * 16 + (lane >> 2) + h * 8;
            if (MODE == 1) {
                int b = m / Nn, n = m - b * Nn;
                grow[mt * 2 + h] = (b * Vv + v) * Nn + n;
            } else {
                grow[mt * 2 + h] = m;
            }
        }
    }
    const int ncol0 = NBase + warpN * 32 + (lane & 3) * 2;
#pragma unroll
    for (int mt = 0; mt < 4; mt++)
#pragma unroll
        for (int nt = 0; nt < 4; nt++) {
            __half2 h01 = __floats2half2_rn(acc[mt][nt][0], acc[mt][nt][1]);
            __half2 h23 = __floats2half2_rn(acc[mt][nt][2], acc[mt][nt][3]);
            *(__half2*)(Cout + (size_t)grow[mt * 2 + 0] * Cc + ncol0 + nt * 8) = h01;
            *(__half2*)(Cout + (size_t)grow[mt * 2 + 1] * Cc + ncol0 + nt * 8) = h23;
        }
}

// ---------------------------------------------------------------------------
// Fused score + softmax + update. One block (256 threads) per (b,n).
// Warps 0..4: per-view dot s_v = tanh(XW1+CW1+b1)·w2 + b2.
// Softmax over views; threads 0..191 do weighted sum of P (fp16) over 5 views.
// Non-last: write c fp16 to g_ch. Last: write fp32 c + r to out.
// ---------------------------------------------------------------------------
__global__ __launch_bounds__(256)
void score_update_kernel(const __half* __restrict__ XW1, const __half* __restrict__ CW1,
                         const float* __restrict__ b1, const float* __restrict__ w2,
                         const float* __restrict__ b2, const __half* __restrict__ P,
                         float* __restrict__ OutC, float* __restrict__ Rout, int last) {
    const int bn = blockIdx.x;
    const int b = bn / Nn, n = bn % Nn;
    const int wid = threadIdx.x >> 5;
    const int lane = threadIdx.x & 31;

    __shared__ float s_sc[Vv];
    __shared__ float s_a[Vv];

    if (wid < Vv) {
        const int row = (b * Vv + wid) * Nn + n;
        const __half* xr = XW1 + (size_t)row * Hh;
        const __half* cr = CW1 + (size_t)bn * Hh;
        float sum = 0.f;
#pragma unroll
        for (int h0 = lane * 8; h0 < Hh; h0 += 256) {
            uint4 xv = *(const uint4*)(xr + h0);
            uint4 cv = *(const uint4*)(cr + h0);
            float bb[8], ww[8];
            *(float4*)&bb[0] = *(const float4*)(b1 + h0);
            *(float4*)&bb[4] = *(const float4*)(b1 + h0 + 4);
            *(float4*)&ww[0] = *(const float4*)(w2 + h0);
            *(float4*)&ww[4] = *(const float4*)(w2 + h0 + 4);
            const __half2* px = (const __half2*)&xv;
            const __half2* pc = (const __half2*)&cv;
#pragma unroll
            for (int j = 0; j < 4; j++) {
                float2 xf = __half22float2(px[j]);
                float2 cf = __half22float2(pc[j]);
                sum += tanhf(xf.x + cf.x + bb[2 * j])     * ww[2 * j];
                sum += tanhf(xf.y + cf.y + bb[2 * j + 1]) * ww[2 * j + 1];
            }
        }
#pragma unroll
        for (int off = 16; off; off >>= 1) sum += __shfl_xor_sync(0xFFFFFFFFu, sum, off);
        if (lane == 0) s_sc[wid] = sum + b2[0];
    }
    __syncthreads();

    if (threadIdx.x == 0) {
        float mx = -1e30f;
#pragma unroll
        for (int v = 0; v < Vv; v++) mx = fmaxf(mx, s_sc[v]);
        float den = 0.f;
        float e[Vv];
#pragma unroll
        for (int v = 0; v < Vv; v++) { e[v] = expf(s_sc[v] - mx); den += e[v]; }
        float inv = 1.0f / den;
#pragma unroll
        for (int v = 0; v < Vv; v++) s_a[v] = e[v] * inv;
        if (last) {
            float ent = 0.f;
#pragma unroll
            for (int v = 0; v < Vv; v++) ent -= s_a[v] * logf(s_a[v] + 1e-8f);
            Rout[bn] = 1.0f - ent / logf((float)Vv);
        }
    }
    __syncthreads();

    const int ch = threadIdx.x * 4;
    if (ch < Cc) {
        float av[Vv];
#pragma unroll
        for (int v = 0; v < Vv; v++) av[v] = s_a[v];
        float4 acc = make_float4(0.f, 0.f, 0.f, 0.f);
#pragma unroll
        for (int v = 0; v < Vv; v++) {
            uint2 pv = *(const uint2*)(P + ((size_t)((b * Vv + v) * Nn + n)) * Cc + ch);
            float2 p01 = __half22float2(*(__half2*)&pv.x);
            float2 p23 = __half22float2(*(__half2*)&pv.y);
            acc.x += av[v] * p01.x; acc.y += av[v] * p01.y;
            acc.z += av[v] * p23.x; acc.w += av[v] * p23.y;
        }
        if (last) {
            *(float4*)(OutC + (size_t)bn * Cc + ch) = acc;
        } else {
            __half2 a = __floats2half2_rn(acc.x, acc.y);
            __half2 bq = __floats2half2_rn(acc.z, acc.w);
            uint2 p;
            p.x = *(uint32_t*)&a;
            p.y = *(uint32_t*)&bq;
            *(uint2*)(g_ch + (size_t)bn * Cc + ch) = p;
        }
    }
}

// ---------------------------------------------------------------------------
// Launch
// ---------------------------------------------------------------------------
extern "C" void kernel_launch(void* const* d_in, const int* in_sizes, int n_in,
                              void* d_out, int out_size) {
    const float* x       = (const float*)d_in[0];
    const float* w_views = (const float*)d_in[1];
    const float* w1      = (const float*)d_in[2];
    const float* b1      = (const float*)d_in[3];
    const float* w2      = (const float*)d_in[4];
    const float* b2      = (const float*)d_in[5];
    float* out = (float*)d_out;   // c [B,N,C] then r [B,N]

    __half *P, *XW1, *CW1, *xh, *ch, *W;
    cudaGetSymbolAddress((void**)&P,   g_P);
    cudaGetSymbolAddress((void**)&XW1, g_XW1);
    cudaGetSymbolAddress((void**)&CW1, g_CW1);
    cudaGetSymbolAddress((void**)&xh,  g_xh);
    cudaGetSymbolAddress((void**)&ch,  g_ch);
    cudaGetSymbolAddress((void**)&W,   g_W);

    cudaFuncSetAttribute(mma_gemm<0>, cudaFuncAttributeMaxDynamicSharedMemorySize, SMEM_TOTAL);
    cudaFuncSetAttribute(mma_gemm<1>, cudaFuncAttributeMaxDynamicSharedMemorySize, SMEM_TOTAL);

    // conversions
    {
        size_t tot = (size_t)BVN * Cc / 4;
        split_x_kernel<<<(unsigned)((tot + 255) / 256), 256>>>(x);
        size_t tw = (size_t)7 * WMAT;
        split_w_kernel<<<(unsigned)((tw + 255) / 256), 256>>>(w_views, w1);
        int tm = BN_ROWS * (Cc / 4);
        mean_kernel<<<(tm + 255) / 256, 256>>>(x);
    }
    // proj_x = x @ w_views (per view)
    {
        dim3 grid(Cc / 128, BN_ROWS / 128, Vv);   // (6, 49, 5)
        mma_gemm<1><<<grid, 256, SMEM_TOTAL>>>(xh, W, P);
    }
    // XW1 = x @ w1[:C]
    {
        dim3 grid(Hh / 128, BVN / 128, 1);        // (6, 245)
        mma_gemm<0><<<grid, 256, SMEM_TOTAL>>>(xh, W + (size_t)5 * WMAT, XW1);
    }
    // iterations
    for (int it = 0; it < NUM_ITERS; it++) {
        dim3 gridc(Hh / 128, BN_ROWS / 128, 1);   // (6, 49)
        mma_gemm<0><<<gridc, 256, SMEM_TOTAL>>>(ch, W + (size_t)6 * WMAT, CW1);

        int last = (it == NUM_ITERS - 1) ? 1 : 0;
        float* rdst = out + (size_t)BN_ROWS * Cc;
        score_update_kernel<<<BN_ROWS, 256>>>(XW1, CW1, b1, w2, b2, P, out, rdst, last);
    }
    (void)in_sizes; (void)n_in; (void)out_size;
}

// round 10
// speedup vs baseline: 2.8335x; 1.0719x over previous
#include <cuda_runtime.h>
#include <cuda_fp16.h>
#include <cstdint>

#define Bb 32
#define Vv 5
#define Nn 196
#define Cc 768
#define Hh 768
#define BN_ROWS 6272            // Bb*Nn
#define BVN 31360               // Bb*Vv*Nn
#define NUM_ITERS 3
#define WMAT (Cc*Cc)            // 589824

// ---------------------------------------------------------------------------
// Scratch (device globals; no runtime allocation allowed) — all fp16
// ---------------------------------------------------------------------------
__device__ __half g_P[(size_t)BVN * Cc];        // proj_x
__device__ __half g_XW1[(size_t)BVN * Hh];      // x @ w1[:C]
__device__ __half g_CW1[(size_t)BN_ROWS * Hh];  // c @ w1[C:]
__device__ __half g_xh[(size_t)BVN * Cc];       // x (fp16)
__device__ __half g_ch[(size_t)BN_ROWS * Cc];   // c (fp16)
// 7 transposed [N,K] weight matrices (fp16): views 0..4, w1a=5, w1b=6
__device__ __half g_W[(size_t)7 * WMAT];

// ---------------------------------------------------------------------------
// Helpers
// ---------------------------------------------------------------------------
__device__ __forceinline__ uint32_t su32(const void* p) {
    uint32_t a;
    asm("{ .reg .u64 t; cvta.to.shared.u64 t, %1; cvt.u32.u64 %0, t; }" : "=r"(a) : "l"(p));
    return a;
}
__device__ __forceinline__ void cpa16(uint32_t d, const void* s) {
    asm volatile("cp.async.cg.shared.global [%0], [%1], 16;" :: "r"(d), "l"(s) : "memory");
}
__device__ __forceinline__ void cp_commit() {
    asm volatile("cp.async.commit_group;" ::: "memory");
}
__device__ __forceinline__ void ldsm4(uint32_t& r0, uint32_t& r1, uint32_t& r2, uint32_t& r3,
                                      uint32_t addr) {
    asm volatile("ldmatrix.sync.aligned.m8n8.x4.shared.b16 {%0,%1,%2,%3}, [%4];"
                 : "=r"(r0), "=r"(r1), "=r"(r2), "=r"(r3) : "r"(addr));
}
__device__ __forceinline__ void mma16816(float* d, const uint32_t* a, const uint32_t* b) {
    asm volatile(
        "mma.sync.aligned.m16n8k16.row.col.f32.f16.f16.f32 "
        "{%0,%1,%2,%3}, {%4,%5,%6,%7}, {%8,%9}, {%0,%1,%2,%3};"
        : "+f"(d[0]), "+f"(d[1]), "+f"(d[2]), "+f"(d[3])
        : "r"(a[0]), "r"(a[1]), "r"(a[2]), "r"(a[3]), "r"(b[0]), "r"(b[1]));
}
__device__ __forceinline__ float tanh_fast(float x) {
    float y;
    asm("tanh.approx.f32 %0, %1;" : "=f"(y) : "f"(x));
    return y;
}

// ---------------------------------------------------------------------------
// Fused: x -> fp16 AND mean over views -> c0 (fp16). One pass over x.
// Thread handles 4 channels of one (b,n) row across all 5 views.
// ---------------------------------------------------------------------------
__global__ void xmean_kernel(const float* __restrict__ x) {
    int i = blockIdx.x * blockDim.x + threadIdx.x;
    const int TOT = BN_ROWS * (Cc / 4);
    if (i >= TOT) return;
    int bn = i / (Cc / 4);
    int cq = (i % (Cc / 4)) * 4;
    int b = bn / Nn, n = bn % Nn;
    float4 acc = make_float4(0.f, 0.f, 0.f, 0.f);
#pragma unroll
    for (int v = 0; v < Vv; v++) {
        size_t row = (size_t)((b * Vv + v) * Nn + n);
        const float4 xv = *(const float4*)(x + row * Cc + cq);
        acc.x += xv.x; acc.y += xv.y; acc.z += xv.z; acc.w += xv.w;
        __half2 a = __floats2half2_rn(xv.x, xv.y);
        __half2 bq = __floats2half2_rn(xv.z, xv.w);
        uint2 p;
        p.x = *(uint32_t*)&a;
        p.y = *(uint32_t*)&bq;
        *(uint2*)(g_xh + row * Cc + cq) = p;
    }
    const float s = 1.0f / Vv;
    __half2 a = __floats2half2_rn(acc.x * s, acc.y * s);
    __half2 bq = __floats2half2_rn(acc.z * s, acc.w * s);
    uint2 p;
    p.x = *(uint32_t*)&a;
    p.y = *(uint32_t*)&bq;
    *(uint2*)(g_ch + (size_t)bn * Cc + cq) = p;
}

// ---------------------------------------------------------------------------
// Transpose weights into g_W ([N,K] K-major, 7 matrices, fp16)
// ---------------------------------------------------------------------------
__global__ void split_w_kernel(const float* __restrict__ w_views, const float* __restrict__ w1) {
    size_t j = (size_t)blockIdx.x * blockDim.x + threadIdx.x;
    const size_t TOT = (size_t)7 * WMAT;
    if (j >= TOT) return;
    int m = (int)(j / WMAT);
    int r = (int)(j % WMAT);
    int n = r / Cc, k = r % Cc;
    float s;
    if (m < 5)       s = w_views[(size_t)m * WMAT + (size_t)k * Cc + n];
    else if (m == 5) s = w1[(size_t)k * Hh + n];
    else             s = w1[(size_t)(Cc + k) * Hh + n];
    g_W[j] = __float2half_rn(s);
}

// ---------------------------------------------------------------------------
// GEMM core config
// ---------------------------------------------------------------------------
#define STAGE_BYTES 32768          // 2 tiles x 16KB (A, B)
#define SMEM_TOTAL  (2 * STAGE_BYTES)
#define OFF_B  16384
#define NCHUNK 12

// ---------------------------------------------------------------------------
// Combined big GEMM: grid (12, 49, 5). v = blockIdx.z selects the per-view
// row gather. bx<6: B=W_v, out=P; bx>=6: B=w1a, out=XW1 (same gathered rows).
// ---------------------------------------------------------------------------
__global__ __launch_bounds__(256, 2)
void mma_gemm_big(const __half* __restrict__ Aw, const __half* __restrict__ Wall,
                  __half* __restrict__ P, __half* __restrict__ XW1) {
    extern __shared__ char smem[];
    const uint32_t sb = su32(smem);
    const int tid = threadIdx.x;
    const int lane = tid & 31;
    const int wid = tid >> 5;
    const int warpM = wid & 1;
    const int warpN = wid >> 1;
    const int v = blockIdx.z;
    const int bx = blockIdx.x;
    const bool isP = bx < 6;
    const int NBase = (isP ? bx : bx - 6) * 128;
    const int MBase = blockIdx.y * 128;
    const __half* Bw = Wall + (size_t)(isP ? v : 5) * WMAT;
    __half* Cout = isP ? P : XW1;

    // ---- load geometry ----
    const int lr = tid >> 1;
    const int lc = (tid & 1) * 64;
    int bn0 = MBase + lr;
    int b0 = bn0 / Nn, n0 = bn0 - b0 * Nn;
    int gaRow = (b0 * Vv + v) * Nn + n0;
    const char* aRowPtr = (const char*)(Aw + (size_t)gaRow * Cc) + lc;
    const char* bRowPtr = (const char*)(Bw + (size_t)(NBase + lr) * Cc) + lc;
    uint32_t so[4];
#pragma unroll
    for (int j = 0; j < 4; j++)
        so[j] = (uint32_t)(lr * 128 + ((lc + j * 16) ^ ((lr & 7) << 4)));

    auto issue = [&](int chunk, int stg) {
        uint32_t base = sb + stg * STAGE_BYTES;
        const char* pa = aRowPtr + chunk * 128;
        const char* pb = bRowPtr + chunk * 128;
#pragma unroll
        for (int j = 0; j < 4; j++) {
            cpa16(base + so[j], pa + j * 16);
            cpa16(base + OFF_B + so[j], pb + j * 16);
        }
        cp_commit();
    };

    float acc[4][4][4];
#pragma unroll
    for (int mt = 0; mt < 4; mt++)
#pragma unroll
        for (int nt = 0; nt < 4; nt++)
#pragma unroll
            for (int e = 0; e < 4; e++) acc[mt][nt][e] = 0.f;

    const uint32_t swz = (uint32_t)((lane & 7) << 4);
    const uint32_t aRow0 = (uint32_t)(warpM * 64 + (lane & 15));
    const uint32_t nRow0 = (uint32_t)(warpN * 32 + (lane & 15));
    const uint32_t halfSel = (uint32_t)((lane >> 4) << 4);

    issue(0, 0);
#pragma unroll 1
    for (int i = 0; i < NCHUNK; i++) {
        int stg = i & 1;
        if (i + 1 < NCHUNK) {
            issue(i + 1, stg ^ 1);
            asm volatile("cp.async.wait_group 1;" ::: "memory");
        } else {
            asm volatile("cp.async.wait_group 0;" ::: "memory");
        }
        __syncthreads();

        uint32_t base = sb + stg * STAGE_BYTES;
#pragma unroll
        for (int k16 = 0; k16 < 4; k16++) {
            const uint32_t bc = (uint32_t)(k16 * 32) + halfSel;
            uint32_t ah[4][4], bh[4][2];
#pragma unroll
            for (int mt = 0; mt < 4; mt++) {
                uint32_t ad = base + (aRow0 + mt * 16) * 128 + (bc ^ swz);
                ldsm4(ah[mt][0], ah[mt][1], ah[mt][2], ah[mt][3], ad);
            }
#pragma unroll
            for (int g = 0; g < 2; g++) {
                uint32_t ad = base + OFF_B + (nRow0 + g * 16) * 128 + (bc ^ swz);
                uint32_t r0, r1, r2, r3;
                ldsm4(r0, r1, r2, r3, ad);
                bh[g * 2 + 0][0] = r0; bh[g * 2 + 0][1] = r2;
                bh[g * 2 + 1][0] = r1; bh[g * 2 + 1][1] = r3;
            }
#pragma unroll
            for (int mt = 0; mt < 4; mt++)
#pragma unroll
                for (int nt = 0; nt < 4; nt++)
                    mma16816(acc[mt][nt], ah[mt], bh[nt]);
        }
        __syncthreads();
    }

    // ---- epilogue (fp16 stores, gathered rows) ----
    int grow[8];
#pragma unroll
    for (int mt = 0; mt < 4; mt++) {
#pragma unroll
        for (int h = 0; h < 2; h++) {
            int m = MBase + warpM * 64 + mt * 16 + (lane >> 2) + h * 8;
            int b = m / Nn, n = m - b * Nn;
            grow[mt * 2 + h] = (b * Vv + v) * Nn + n;
        }
    }
    const int ncol0 = NBase + warpN * 32 + (lane & 3) * 2;
#pragma unroll
    for (int mt = 0; mt < 4; mt++)
#pragma unroll
        for (int nt = 0; nt < 4; nt++) {
            __half2 h01 = __floats2half2_rn(acc[mt][nt][0], acc[mt][nt][1]);
            __half2 h23 = __floats2half2_rn(acc[mt][nt][2], acc[mt][nt][3]);
            *(__half2*)(Cout + (size_t)grow[mt * 2 + 0] * Cc + ncol0 + nt * 8) = h01;
            *(__half2*)(Cout + (size_t)grow[mt * 2 + 1] * Cc + ncol0 + nt * 8) = h23;
        }
}

// ---------------------------------------------------------------------------
// Flat GEMM for CW1 = c @ w1b. CTA 128x128, flat rows.
// ---------------------------------------------------------------------------
__global__ __launch_bounds__(256, 2)
void mma_gemm_flat(const __half* __restrict__ Aw, const __half* __restrict__ Bw,
                   __half* __restrict__ Cout) {
    extern __shared__ char smem[];
    const uint32_t sb = su32(smem);
    const int tid = threadIdx.x;
    const int lane = tid & 31;
    const int wid = tid >> 5;
    const int warpM = wid & 1;
    const int warpN = wid >> 1;
    const int MBase = blockIdx.y * 128;
    const int NBase = blockIdx.x * 128;

    const int lr = tid >> 1;
    const int lc = (tid & 1) * 64;
    const char* aRowPtr = (const char*)(Aw + (size_t)(MBase + lr) * Cc) + lc;
    const char* bRowPtr = (const char*)(Bw + (size_t)(NBase + lr) * Cc) + lc;
    uint32_t so[4];
#pragma unroll
    for (int j = 0; j < 4; j++)
        so[j] = (uint32_t)(lr * 128 + ((lc + j * 16) ^ ((lr & 7) << 4)));

    auto issue = [&](int chunk, int stg) {
        uint32_t base = sb + stg * STAGE_BYTES;
        const char* pa = aRowPtr + chunk * 128;
        const char* pb = bRowPtr + chunk * 128;
#pragma unroll
        for (int j = 0; j < 4; j++) {
            cpa16(base + so[j], pa + j * 16);
            cpa16(base + OFF_B + so[j], pb + j * 16);
        }
        cp_commit();
    };

    float acc[4][4][4];
#pragma unroll
    for (int mt = 0; mt < 4; mt++)
#pragma unroll
        for (int nt = 0; nt < 4; nt++)
#pragma unroll
            for (int e = 0; e < 4; e++) acc[mt][nt][e] = 0.f;

    const uint32_t swz = (uint32_t)((lane & 7) << 4);
    const uint32_t aRow0 = (uint32_t)(warpM * 64 + (lane & 15));
    const uint32_t nRow0 = (uint32_t)(warpN * 32 + (lane & 15));
    const uint32_t halfSel = (uint32_t)((lane >> 4) << 4);

    issue(0, 0);
#pragma unroll 1
    for (int i = 0; i < NCHUNK; i++) {
        int stg = i & 1;
        if (i + 1 < NCHUNK) {
            issue(i + 1, stg ^ 1);
            asm volatile("cp.async.wait_group 1;" ::: "memory");
        } else {
            asm volatile("cp.async.wait_group 0;" ::: "memory");
        }
        __syncthreads();

        uint32_t base = sb + stg * STAGE_BYTES;
#pragma unroll
        for (int k16 = 0; k16 < 4; k16++) {
            const uint32_t bc = (uint32_t)(k16 * 32) + halfSel;
            uint32_t ah[4][4], bh[4][2];
#pragma unroll
            for (int mt = 0; mt < 4; mt++) {
                uint32_t ad = base + (aRow0 + mt * 16) * 128 + (bc ^ swz);
                ldsm4(ah[mt][0], ah[mt][1], ah[mt][2], ah[mt][3], ad);
            }
#pragma unroll
            for (int g = 0; g < 2; g++) {
                uint32_t ad = base + OFF_B + (nRow0 + g * 16) * 128 + (bc ^ swz);
                uint32_t r0, r1, r2, r3;
                ldsm4(r0, r1, r2, r3, ad);
                bh[g * 2 + 0][0] = r0; bh[g * 2 + 0][1] = r2;
                bh[g * 2 + 1][0] = r1; bh[g * 2 + 1][1] = r3;
            }
#pragma unroll
            for (int mt = 0; mt < 4; mt++)
#pragma unroll
                for (int nt = 0; nt < 4; nt++)
                    mma16816(acc[mt][nt], ah[mt], bh[nt]);
        }
        __syncthreads();
    }

    const int ncol0 = NBase + warpN * 32 + (lane & 3) * 2;
#pragma unroll
    for (int mt = 0; mt < 4; mt++) {
        int m0 = MBase + warpM * 64 + mt * 16 + (lane >> 2);
#pragma unroll
        for (int nt = 0; nt < 4; nt++) {
            __half2 h01 = __floats2half2_rn(acc[mt][nt][0], acc[mt][nt][1]);
            __half2 h23 = __floats2half2_rn(acc[mt][nt][2], acc[mt][nt][3]);
            *(__half2*)(Cout + (size_t)m0 * Cc + ncol0 + nt * 8) = h01;
            *(__half2*)(Cout + (size_t)(m0 + 8) * Cc + ncol0 + nt * 8) = h23;
        }
    }
}

// ---------------------------------------------------------------------------
// Fused score + softmax + update. One block (256 threads) per (b,n).
// tanh.approx + __expf/__logf fast math.
// ---------------------------------------------------------------------------
__global__ __launch_bounds__(256)
void score_update_kernel(const __half* __restrict__ XW1, const __half* __restrict__ CW1,
                         const float* __restrict__ b1, const float* __restrict__ w2,
                         const float* __restrict__ b2, const __half* __restrict__ P,
                         float* __restrict__ OutC, float* __restrict__ Rout, int last) {
    const int bn = blockIdx.x;
    const int b = bn / Nn, n = bn % Nn;
    const int wid = threadIdx.x >> 5;
    const int lane = threadIdx.x & 31;

    __shared__ float s_sc[Vv];
    __shared__ float s_a[Vv];

    if (wid < Vv) {
        const int row = (b * Vv + wid) * Nn + n;
        const __half* xr = XW1 + (size_t)row * Hh;
        const __half* cr = CW1 + (size_t)bn * Hh;
        float sum = 0.f;
#pragma unroll
        for (int h0 = lane * 8; h0 < Hh; h0 += 256) {
            uint4 xv = *(const uint4*)(xr + h0);
            uint4 cv = *(const uint4*)(cr + h0);
            float bb[8], ww[8];
            *(float4*)&bb[0] = *(const float4*)(b1 + h0);
            *(float4*)&bb[4] = *(const float4*)(b1 + h0 + 4);
            *(float4*)&ww[0] = *(const float4*)(w2 + h0);
            *(float4*)&ww[4] = *(const float4*)(w2 + h0 + 4);
            const __half2* px = (const __half2*)&xv;
            const __half2* pc = (const __half2*)&cv;
#pragma unroll
            for (int j = 0; j < 4; j++) {
                float2 xf = __half22float2(px[j]);
                float2 cf = __half22float2(pc[j]);
                sum += tanh_fast(xf.x + cf.x + bb[2 * j])     * ww[2 * j];
                sum += tanh_fast(xf.y + cf.y + bb[2 * j + 1]) * ww[2 * j + 1];
            }
        }
#pragma unroll
        for (int off = 16; off; off >>= 1) sum += __shfl_xor_sync(0xFFFFFFFFu, sum, off);
        if (lane == 0) s_sc[wid] = sum + b2[0];
    }
    __syncthreads();

    if (threadIdx.x == 0) {
        float mx = -1e30f;
#pragma unroll
        for (int v = 0; v < Vv; v++) mx = fmaxf(mx, s_sc[v]);
        float den = 0.f;
        float e[Vv];
#pragma unroll
        for (int v = 0; v < Vv; v++) { e[v] = __expf(s_sc[v] - mx); den += e[v]; }
        float inv = 1.0f / den;
#pragma unroll
        for (int v = 0; v < Vv; v++) s_a[v] = e[v] * inv;
        if (last) {
            float ent = 0.f;
#pragma unroll
            for (int v = 0; v < Vv; v++) ent -= s_a[v] * __logf(s_a[v] + 1e-8f);
            Rout[bn] = 1.0f - ent * (1.0f / 1.6094379124341003f);  // 1/log(5)
        }
    }
    __syncthreads();

    const int ch = threadIdx.x * 4;
    if (ch < Cc) {
        float av[Vv];
#pragma unroll
        for (int v = 0; v < Vv; v++) av[v] = s_a[v];
        float4 acc = make_float4(0.f, 0.f, 0.f, 0.f);
#pragma unroll
        for (int v = 0; v < Vv; v++) {
            uint2 pv = *(const uint2*)(P + ((size_t)((b * Vv + v) * Nn + n)) * Cc + ch);
            float2 p01 = __half22float2(*(__half2*)&pv.x);
            float2 p23 = __half22float2(*(__half2*)&pv.y);
            acc.x += av[v] * p01.x; acc.y += av[v] * p01.y;
            acc.z += av[v] * p23.x; acc.w += av[v] * p23.y;
        }
        if (last) {
            *(float4*)(OutC + (size_t)bn * Cc + ch) = acc;
        } else {
            __half2 a = __floats2half2_rn(acc.x, acc.y);
            __half2 bq = __floats2half2_rn(acc.z, acc.w);
            uint2 p;
            p.x = *(uint32_t*)&a;
            p.y = *(uint32_t*)&bq;
            *(uint2*)(g_ch + (size_t)bn * Cc + ch) = p;
        }
    }
}

// ---------------------------------------------------------------------------
// Launch
// ---------------------------------------------------------------------------
extern "C" void kernel_launch(void* const* d_in, const int* in_sizes, int n_in,
                              void* d_out, int out_size) {
    const float* x       = (const float*)d_in[0];
    const float* w_views = (const float*)d_in[1];
    const float* w1      = (const float*)d_in[2];
    const float* b1      = (const float*)d_in[3];
    const float* w2      = (const float*)d_in[4];
    const float* b2      = (const float*)d_in[5];
    float* out = (float*)d_out;   // c [B,N,C] then r [B,N]

    __half *P, *XW1, *CW1, *xh, *ch, *W;
    cudaGetSymbolAddress((void**)&P,   g_P);
    cudaGetSymbolAddress((void**)&XW1, g_XW1);
    cudaGetSymbolAddress((void**)&CW1, g_CW1);
    cudaGetSymbolAddress((void**)&xh,  g_xh);
    cudaGetSymbolAddress((void**)&ch,  g_ch);
    cudaGetSymbolAddress((void**)&W,   g_W);

    cudaFuncSetAttribute(mma_gemm_big,  cudaFuncAttributeMaxDynamicSharedMemorySize, SMEM_TOTAL);
    cudaFuncSetAttribute(mma_gemm_flat, cudaFuncAttributeMaxDynamicSharedMemorySize, SMEM_TOTAL);

    // conversions (x read once)
    {
        size_t tw = (size_t)7 * WMAT;
        split_w_kernel<<<(unsigned)((tw + 255) / 256), 256>>>(w_views, w1);
        int tm = BN_ROWS * (Cc / 4);
        xmean_kernel<<<(tm + 255) / 256, 256>>>(x);
    }
    // P = x @ w_views and XW1 = x @ w1[:C] in one launch
    {
        dim3 grid(12, BN_ROWS / 128, Vv);   // (12, 49, 5)
        mma_gemm_big<<<grid, 256, SMEM_TOTAL>>>(xh, W, P, XW1);
    }
    // iterations
    for (int it = 0; it < NUM_ITERS; it++) {
        dim3 gridc(Hh / 128, BN_ROWS / 128);   // (6, 49)
        mma_gemm_flat<<<gridc, 256, SMEM_TOTAL>>>(ch, W + (size_t)6 * WMAT, CW1);

        int last = (it == NUM_ITERS - 1) ? 1 : 0;
        float* rdst = out + (size_t)BN_ROWS * Cc;
        score_update_kernel<<<BN_ROWS, 256>>>(XW1, CW1, b1, w2, b2, P, out, rdst, last);
    }
    (void)in_sizes; (void)n_in; (void)out_size;
}